// round 4
// baseline (speedup 1.0000x reference)
#include <cuda_runtime.h>
#include <math.h>

// ----------------------------------------------------------------------------
// EdgeBiasedAttention — TF32 tensor-core, v4.
// Attention block = 32 queries x ALL 8 heads (256 thr, warp = head).
// Edge/mask staged once per (b,q-tile); conflict-free fragment LDS.
// B=32, N=512, D=256, H=8, HD=32
// ----------------------------------------------------------------------------

#define BATCH 32
#define NSEQ  512
#define DMODEL 256
#define NHEAD 8
#define HDIM  32
#define MROWS (BATCH * NSEQ)  // 16384

__device__ float g_q [MROWS * DMODEL];
__device__ float g_k [MROWS * DMODEL];
__device__ float g_v [MROWS * DMODEL];
__device__ float g_ao[MROWS * DMODEL];

__device__ __forceinline__ unsigned f2tf(float x) {
    unsigned r;
    asm("cvt.rna.tf32.f32 %0, %1;" : "=r"(r) : "f"(x));
    return r;
}

__device__ __forceinline__ void mma_tf32(float c[4],
                                         unsigned a0, unsigned a1, unsigned a2, unsigned a3,
                                         unsigned b0, unsigned b1)
{
    asm volatile(
        "mma.sync.aligned.m16n8k8.row.col.f32.tf32.tf32.f32 "
        "{%0,%1,%2,%3}, {%4,%5,%6,%7}, {%8,%9}, {%0,%1,%2,%3};"
        : "+f"(c[0]), "+f"(c[1]), "+f"(c[2]), "+f"(c[3])
        : "r"(a0), "r"(a1), "r"(a2), "r"(a3), "r"(b0), "r"(b1));
}

// ----------------------------------------------------------------------------
// TF32 GEMM (proven in R2): C[M,256] = X[M,256] @ W[256,256]^T
// ----------------------------------------------------------------------------
#define GLDK 36

__global__ __launch_bounds__(256) void gemm_tf32(const float* __restrict__ X,
                                                 const float* __restrict__ W,
                                                 float* __restrict__ C)
{
    __shared__ unsigned Xs[128 * GLDK];
    __shared__ unsigned Ws[128 * GLDK];

    const int t    = threadIdx.x;
    const int warp = t >> 5, lane = t & 31;
    const int g    = lane >> 2, l = lane & 3;
    const int m0   = blockIdx.y * 128;
    const int n0   = blockIdx.x * 128;
    const int wm   = (warp >> 2) * 64;
    const int wn   = (warp & 3) * 32;

    float acc[4][4][4];
#pragma unroll
    for (int mt = 0; mt < 4; ++mt)
#pragma unroll
        for (int nt = 0; nt < 4; ++nt)
#pragma unroll
            for (int i = 0; i < 4; ++i) acc[mt][nt][i] = 0.f;

    for (int k0 = 0; k0 < DMODEL; k0 += 32) {
#pragma unroll
        for (int i = 0; i < 4; ++i) {
            int idx = t + i * 256;
            int row = idx >> 3, c4 = idx & 7;
            float4 xv = *(const float4*)(X + (size_t)(m0 + row) * DMODEL + k0 + c4 * 4);
            unsigned* xd = &Xs[row * GLDK + c4 * 4];
            xd[0] = f2tf(xv.x); xd[1] = f2tf(xv.y); xd[2] = f2tf(xv.z); xd[3] = f2tf(xv.w);
            float4 wv = *(const float4*)(W + (size_t)(n0 + row) * DMODEL + k0 + c4 * 4);
            unsigned* wd = &Ws[row * GLDK + c4 * 4];
            wd[0] = f2tf(wv.x); wd[1] = f2tf(wv.y); wd[2] = f2tf(wv.z); wd[3] = f2tf(wv.w);
        }
        __syncthreads();

#pragma unroll
        for (int ks = 0; ks < 4; ++ks) {
            const int k = ks * 8;
            unsigned a[4][4];
#pragma unroll
            for (int mt = 0; mt < 4; ++mt) {
                int r = wm + mt * 16;
                a[mt][0] = Xs[(r + g) * GLDK + k + l];
                a[mt][1] = Xs[(r + g + 8) * GLDK + k + l];
                a[mt][2] = Xs[(r + g) * GLDK + k + l + 4];
                a[mt][3] = Xs[(r + g + 8) * GLDK + k + l + 4];
            }
            unsigned b[4][2];
#pragma unroll
            for (int nt = 0; nt < 4; ++nt) {
                int cn = wn + nt * 8;
                b[nt][0] = Ws[(cn + g) * GLDK + k + l];
                b[nt][1] = Ws[(cn + g) * GLDK + k + l + 4];
            }
#pragma unroll
            for (int mt = 0; mt < 4; ++mt)
#pragma unroll
                for (int nt = 0; nt < 4; ++nt)
                    mma_tf32(acc[mt][nt], a[mt][0], a[mt][1], a[mt][2], a[mt][3],
                             b[nt][0], b[nt][1]);
        }
        __syncthreads();
    }

#pragma unroll
    for (int mt = 0; mt < 4; ++mt) {
#pragma unroll
        for (int nt = 0; nt < 4; ++nt) {
            int r = m0 + wm + mt * 16 + g;
            int c = n0 + wn + nt * 8 + 2 * l;
            *(float2*)(C + (size_t)r * DMODEL + c)       = make_float2(acc[mt][nt][0], acc[mt][nt][1]);
            *(float2*)(C + (size_t)(r + 8) * DMODEL + c) = make_float2(acc[mt][nt][2], acc[mt][nt][3]);
        }
    }
}

// ----------------------------------------------------------------------------
// Attention v4: block = 32 queries x 8 heads, 256 threads (8 warps).
// Warp w = head w, 32 q-rows (2 m16 tiles). Keys streamed in tiles of 32.
// K/V tiles hold all 256 model cols; edge/mask staged once for all heads.
// ----------------------------------------------------------------------------
#define KT   32    // key tile
#define KLD 260    // K (and staged-Q) row stride: banks 4g+l  -> conflict-free
#define VLD 264    // V row stride: banks 8l+g -> conflict-free
#define ELD  36    // edge tile stride (floats)
#define PLD  36    // per-warp P stride
#define MLD  36    // mask byte stride

#define OFF_V (KT * KLD)                           // 8320 words
#define OFF_E (OFF_V + KT * VLD)                   // 16768
#define OFF_P (OFF_E + 32 * ELD)                   // 17920
#define OFF_M_BYTES ((OFF_P + 8 * 32 * PLD) * 4)   // (17920+9216)*4 = 108544
#define SMEM_BYTES (OFF_M_BYTES + 32 * MLD)        // 109696

__global__ __launch_bounds__(256, 2) void attn_v4(
    const float* __restrict__ Q, const float* __restrict__ K,
    const float* __restrict__ V, const float* __restrict__ edge,
    const int*   __restrict__ mask, const float* __restrict__ We,
    float* __restrict__ AO)
{
    extern __shared__ unsigned sm[];
    unsigned* Ks = sm;                       // KT x KLD (also Q staging temp, 32x256)
    unsigned* Vs = sm + OFF_V;               // KT x VLD
    float*    Es = (float*)(sm + OFF_E);     // 32 x ELD
    float*    Ps = (float*)(sm + OFF_P);     // 8 warps x 32 x PLD
    unsigned char* Ms = (unsigned char*)sm + OFF_M_BYTES;  // 32 x MLD

    const int t    = threadIdx.x;
    const int warp = t >> 5, lane = t & 31;
    const int g    = lane >> 2, l = lane & 3;
    const int b    = blockIdx.y;
    const int q0   = blockIdx.x * 32;
    const int hd   = warp;                   // one warp per head
    const int hoff = warp * HDIM;            // head col offset inside 256
    const float we = We[hd];
    const float scale = 0.17677669529663687f;

    // ---- stage Q tile (32 x 256) into Ks temp, pull fragments to registers
#pragma unroll
    for (int i = 0; i < 8; ++i) {
        int idx = t + i * 256;               // 0..2047
        int row = idx >> 6, c4 = idx & 63;
        float4 qv = *(const float4*)(Q + ((size_t)(b * NSEQ + q0 + row)) * DMODEL + c4 * 4);
        *(uint4*)&Ks[row * KLD + c4 * 4] =
            make_uint4(f2tf(qv.x), f2tf(qv.y), f2tf(qv.z), f2tf(qv.w));
    }
    __syncthreads();

    unsigned qf[2][4][4];
#pragma unroll
    for (int mt = 0; mt < 2; ++mt)
#pragma unroll
        for (int ks = 0; ks < 4; ++ks) {
            int r = mt * 16;
            qf[mt][ks][0] = Ks[(r + g) * KLD + hoff + ks * 8 + l];
            qf[mt][ks][1] = Ks[(r + g + 8) * KLD + hoff + ks * 8 + l];
            qf[mt][ks][2] = Ks[(r + g) * KLD + hoff + ks * 8 + l + 4];
            qf[mt][ks][3] = Ks[(r + g + 8) * KLD + hoff + ks * 8 + l + 4];
        }
    __syncthreads();

    float mrow[2][2], lrow[2][2];
    float o[2][4][4];
#pragma unroll
    for (int mt = 0; mt < 2; ++mt) {
        mrow[mt][0] = -1e30f; mrow[mt][1] = -1e30f;
        lrow[mt][0] = 0.f;    lrow[mt][1] = 0.f;
#pragma unroll
        for (int nt = 0; nt < 4; ++nt)
#pragma unroll
            for (int i = 0; i < 4; ++i) o[mt][nt][i] = 0.f;
    }

    float* Pw = Ps + warp * 32 * PLD;

    for (int jt = 0; jt < NSEQ; jt += KT) {
        // ---- stage K, V (KT x 256 each, all heads)
#pragma unroll
        for (int i = 0; i < 8; ++i) {
            int idx = t + i * 256;           // 0..2047
            int row = idx >> 6, c4 = idx & 63;
            size_t goff = ((size_t)(b * NSEQ + jt + row)) * DMODEL + c4 * 4;
            float4 kv = *(const float4*)(K + goff);
            *(uint4*)&Ks[row * KLD + c4 * 4] =
                make_uint4(f2tf(kv.x), f2tf(kv.y), f2tf(kv.z), f2tf(kv.w));
            float4 vv = *(const float4*)(V + goff);
            *(uint4*)&Vs[row * VLD + c4 * 4] =
                make_uint4(f2tf(vv.x), f2tf(vv.y), f2tf(vv.z), f2tf(vv.w));
        }
        // ---- stage edge (32 x 32) + mask bytes (32 x 32), shared by all heads
        {
            int row = t >> 3, c4 = t & 7;    // 256 threads = 32x8 float4 chunks
            size_t goff = ((size_t)(b * NSEQ + q0 + row)) * NSEQ + jt + c4 * 4;
            *(float4*)&Es[row * ELD + c4 * 4] = *(const float4*)(edge + goff);
            int4 mv = *(const int4*)(mask + goff);
            unsigned char* md = Ms + row * MLD + c4 * 4;
            md[0] = mv.x ? 1 : 0; md[1] = mv.y ? 1 : 0;
            md[2] = mv.z ? 1 : 0; md[3] = mv.w ? 1 : 0;
        }
        __syncthreads();

        // ---- S = Q @ K^T  (32 q-rows x 32 keys, this warp's head)
        float s[2][4][4];
#pragma unroll
        for (int mt = 0; mt < 2; ++mt)
#pragma unroll
            for (int nt = 0; nt < 4; ++nt)
#pragma unroll
                for (int i = 0; i < 4; ++i) s[mt][nt][i] = 0.f;

#pragma unroll
        for (int ks = 0; ks < 4; ++ks) {
            const int k = ks * 8;
#pragma unroll
            for (int nt = 0; nt < 4; ++nt) {
                unsigned b0 = Ks[(nt * 8 + g) * KLD + hoff + k + l];
                unsigned b1 = Ks[(nt * 8 + g) * KLD + hoff + k + l + 4];
                mma_tf32(s[0][nt], qf[0][ks][0], qf[0][ks][1], qf[0][ks][2], qf[0][ks][3], b0, b1);
                mma_tf32(s[1][nt], qf[1][ks][0], qf[1][ks][1], qf[1][ks][2], qf[1][ks][3], b0, b1);
            }
        }

        __syncwarp();   // prior PV fragment reads done before P overwrite

        // ---- epilogue: bias + mask + online softmax; write P (warp-local)
#pragma unroll
        for (int mt = 0; mt < 2; ++mt) {
            const int r0 = mt * 16 + g;
            float mn0 = mrow[mt][0], mn1 = mrow[mt][1];
#pragma unroll
            for (int nt = 0; nt < 4; ++nt) {
                int c = nt * 8 + 2 * l;
                float2 e01 = *(float2*)&Es[r0 * ELD + c];
                float2 e23 = *(float2*)&Es[(r0 + 8) * ELD + c];
                const unsigned char* mb0 = Ms + r0 * MLD + c;
                const unsigned char* mb2 = Ms + (r0 + 8) * MLD + c;
                s[mt][nt][0] = mb0[0] ? s[mt][nt][0] * scale + we * e01.x : -1e30f;
                s[mt][nt][1] = mb0[1] ? s[mt][nt][1] * scale + we * e01.y : -1e30f;
                s[mt][nt][2] = mb2[0] ? s[mt][nt][2] * scale + we * e23.x : -1e30f;
                s[mt][nt][3] = mb2[1] ? s[mt][nt][3] * scale + we * e23.y : -1e30f;
                mn0 = fmaxf(mn0, fmaxf(s[mt][nt][0], s[mt][nt][1]));
                mn1 = fmaxf(mn1, fmaxf(s[mt][nt][2], s[mt][nt][3]));
            }
            mn0 = fmaxf(mn0, __shfl_xor_sync(0xffffffff, mn0, 1));
            mn0 = fmaxf(mn0, __shfl_xor_sync(0xffffffff, mn0, 2));
            mn1 = fmaxf(mn1, __shfl_xor_sync(0xffffffff, mn1, 1));
            mn1 = fmaxf(mn1, __shfl_xor_sync(0xffffffff, mn1, 2));

            float corr0 = __expf(mrow[mt][0] - mn0);
            float corr1 = __expf(mrow[mt][1] - mn1);
            mrow[mt][0] = mn0; mrow[mt][1] = mn1;

            float ps0 = 0.f, ps1 = 0.f;
#pragma unroll
            for (int nt = 0; nt < 4; ++nt) {
                float p0 = __expf(s[mt][nt][0] - mn0);
                float p1 = __expf(s[mt][nt][1] - mn0);
                float p2 = __expf(s[mt][nt][2] - mn1);
                float p3 = __expf(s[mt][nt][3] - mn1);
                ps0 += p0 + p1; ps1 += p2 + p3;
                int c = nt * 8 + 2 * l;
                Pw[r0 * PLD + c]           = __uint_as_float(f2tf(p0));
                Pw[r0 * PLD + c + 1]       = __uint_as_float(f2tf(p1));
                Pw[(r0 + 8) * PLD + c]     = __uint_as_float(f2tf(p2));
                Pw[(r0 + 8) * PLD + c + 1] = __uint_as_float(f2tf(p3));
            }
            ps0 += __shfl_xor_sync(0xffffffff, ps0, 1);
            ps0 += __shfl_xor_sync(0xffffffff, ps0, 2);
            ps1 += __shfl_xor_sync(0xffffffff, ps1, 1);
            ps1 += __shfl_xor_sync(0xffffffff, ps1, 2);
            lrow[mt][0] = lrow[mt][0] * corr0 + ps0;
            lrow[mt][1] = lrow[mt][1] * corr1 + ps1;
#pragma unroll
            for (int nt = 0; nt < 4; ++nt) {
                o[mt][nt][0] *= corr0; o[mt][nt][1] *= corr0;
                o[mt][nt][2] *= corr1; o[mt][nt][3] *= corr1;
            }
        }
        __syncwarp();

        // ---- O += P @ V
#pragma unroll
        for (int ks2 = 0; ks2 < 4; ++ks2) {
            const int k = ks2 * 8;
            unsigned a[2][4];
#pragma unroll
            for (int mt = 0; mt < 2; ++mt) {
                int r = mt * 16;
                a[mt][0] = __float_as_uint(Pw[(r + g) * PLD + k + l]);
                a[mt][1] = __float_as_uint(Pw[(r + g + 8) * PLD + k + l]);
                a[mt][2] = __float_as_uint(Pw[(r + g) * PLD + k + l + 4]);
                a[mt][3] = __float_as_uint(Pw[(r + g + 8) * PLD + k + l + 4]);
            }
#pragma unroll
            for (int nt = 0; nt < 4; ++nt) {
                unsigned b0 = Vs[(k + l) * VLD + hoff + nt * 8 + g];
                unsigned b1 = Vs[(k + l + 4) * VLD + hoff + nt * 8 + g];
                mma_tf32(o[0][nt], a[0][0], a[0][1], a[0][2], a[0][3], b0, b1);
                mma_tf32(o[1][nt], a[1][0], a[1][1], a[1][2], a[1][3], b0, b1);
            }
        }
        __syncthreads();
    }

    // ---- write output
#pragma unroll
    for (int mt = 0; mt < 2; ++mt) {
        const float inv0 = 1.0f / lrow[mt][0];
        const float inv1 = 1.0f / lrow[mt][1];
#pragma unroll
        for (int nt = 0; nt < 4; ++nt) {
            int r = q0 + mt * 16 + g;
            int c = hd * HDIM + nt * 8 + 2 * l;
            *(float2*)(AO + ((size_t)(b * NSEQ + r)) * DMODEL + c) =
                make_float2(o[mt][nt][0] * inv0, o[mt][nt][1] * inv0);
            *(float2*)(AO + ((size_t)(b * NSEQ + r + 8)) * DMODEL + c) =
                make_float2(o[mt][nt][2] * inv1, o[mt][nt][3] * inv1);
        }
    }
}

// ----------------------------------------------------------------------------
// launch
// ----------------------------------------------------------------------------
extern "C" void kernel_launch(void* const* d_in, const int* in_sizes, int n_in,
                              void* d_out, int out_size)
{
    const float* h    = (const float*)d_in[0];
    const float* edge = (const float*)d_in[1];
    const int*   mask = (const int*)  d_in[2];
    const float* Wq   = (const float*)d_in[3];
    const float* Wk   = (const float*)d_in[4];
    const float* Wv   = (const float*)d_in[5];
    const float* We   = (const float*)d_in[6];
    const float* Wo   = (const float*)d_in[7];
    float* out = (float*)d_out;

    float *qs, *ks, *vs, *ao;
    cudaGetSymbolAddress((void**)&qs, g_q);
    cudaGetSymbolAddress((void**)&ks, g_k);
    cudaGetSymbolAddress((void**)&vs, g_v);
    cudaGetSymbolAddress((void**)&ao, g_ao);

    cudaFuncSetAttribute(attn_v4, cudaFuncAttributeMaxDynamicSharedMemorySize, SMEM_BYTES);

    dim3 pgrid(DMODEL / 128, MROWS / 128);
    gemm_tf32<<<pgrid, 256>>>(h, Wq, qs);
    gemm_tf32<<<pgrid, 256>>>(h, Wk, ks);
    gemm_tf32<<<pgrid, 256>>>(h, Wv, vs);

    attn_v4<<<dim3(NSEQ / 32, BATCH), 256, SMEM_BYTES>>>(qs, ks, vs, edge, mask, We, ao);

    gemm_tf32<<<pgrid, 256>>>(ao, Wo, out);
}

// round 5
// speedup vs baseline: 1.7977x; 1.7977x over previous
#include <cuda_runtime.h>
#include <cuda_fp16.h>
#include <math.h>

// ----------------------------------------------------------------------------
// EdgeBiasedAttention — fp16 mma.m16n8k16 pipeline (v5)
// B=32, N=512, D=256, H=8, HD=32
// ----------------------------------------------------------------------------

#define BATCH 32
#define NSEQ  512
#define DMODEL 256
#define NHEAD 8
#define HDIM  32
#define MROWS (BATCH * NSEQ)  // 16384

// fp16 scratch
__device__ __half g_h16 [MROWS * DMODEL];
__device__ __half g_q16 [MROWS * DMODEL];
__device__ __half g_k16 [MROWS * DMODEL];
__device__ __half g_v16 [MROWS * DMODEL];
__device__ __half g_ao16[MROWS * DMODEL];
__device__ __half g_em  [BATCH * NSEQ * NSEQ];   // masked edge (NaN = masked)
__device__ __half g_w16 [4 * DMODEL * DMODEL];   // Wq, Wk, Wv, Wo fp16

// ---------------- helpers ----------------
__device__ __forceinline__ void mma_f16(float c[4],
                                        unsigned a0, unsigned a1, unsigned a2, unsigned a3,
                                        unsigned b0, unsigned b1)
{
    asm volatile(
        "mma.sync.aligned.m16n8k16.row.col.f32.f16.f16.f32 "
        "{%0,%1,%2,%3}, {%4,%5,%6,%7}, {%8,%9}, {%0,%1,%2,%3};"
        : "+f"(c[0]), "+f"(c[1]), "+f"(c[2]), "+f"(c[3])
        : "r"(a0), "r"(a1), "r"(a2), "r"(a3), "r"(b0), "r"(b1));
}

__device__ __forceinline__ unsigned f2h2(float a, float b) {
    __half2 h = __floats2half2_rn(a, b);
    return *(unsigned*)&h;
}

__device__ __forceinline__ void cp16(void* sdst, const void* gsrc) {
    unsigned s = (unsigned)__cvta_generic_to_shared(sdst);
    asm volatile("cp.async.cg.shared.global [%0], [%1], 16;" :: "r"(s), "l"(gsrc));
}
#define CP_COMMIT() asm volatile("cp.async.commit_group;")
#define CP_WAIT0()  asm volatile("cp.async.wait_group 0;" ::: "memory")

__device__ __forceinline__ void ldsm4t(unsigned& r0, unsigned& r1, unsigned& r2, unsigned& r3,
                                       const __half* p)
{
    unsigned s = (unsigned)__cvta_generic_to_shared(p);
    asm volatile("ldmatrix.sync.aligned.m8n8.x4.trans.shared.b16 {%0,%1,%2,%3}, [%4];"
                 : "=r"(r0), "=r"(r1), "=r"(r2), "=r"(r3) : "r"(s));
}

// ---------------- preprocessing ----------------
__global__ void prep_f2h(const float* __restrict__ src, __half* __restrict__ dst, int n4)
{
    int i = blockIdx.x * 256 + threadIdx.x;
    if (i < n4) {
        float4 v = ((const float4*)src)[i];
        __half2* d = (__half2*)dst + (size_t)i * 2;
        d[0] = __floats2half2_rn(v.x, v.y);
        d[1] = __floats2half2_rn(v.z, v.w);
    }
}

__global__ void prep_em(const float* __restrict__ edge, const int* __restrict__ mask,
                        __half* __restrict__ em, int n4)
{
    const float QNAN = __int_as_float(0x7fc00000);
    int i = blockIdx.x * 256 + threadIdx.x;
    if (i < n4) {
        float4 e = ((const float4*)edge)[i];
        int4   m = ((const int4*)mask)[i];
        __half2* d = (__half2*)em + (size_t)i * 2;
        d[0] = __floats2half2_rn(m.x ? e.x : QNAN, m.y ? e.y : QNAN);
        d[1] = __floats2half2_rn(m.z ? e.z : QNAN, m.w ? e.w : QNAN);
    }
}

// ----------------------------------------------------------------------------
// fp16 GEMM: C[M,256] = X[M,256] @ W[256,256]^T, both inputs fp16.
// Block 128x128, BK=32, 8 panels, cp.async double-buffered.
// smem row stride 40 halves (80B, conflict-free fragment reads).
// ----------------------------------------------------------------------------
template<bool HALF_OUT>
__global__ __launch_bounds__(256, 2) void gemm_f16(const __half* __restrict__ X,
                                                   const __half* __restrict__ W,
                                                   void* __restrict__ Cout)
{
    __shared__ __half Xs[2][128 * 40];
    __shared__ __half Ws[2][128 * 40];

    const int t = threadIdx.x, warp = t >> 5, lane = t & 31;
    const int g = lane >> 2, l = lane & 3;
    const int m0 = blockIdx.y * 128, n0 = blockIdx.x * 128;
    const int wm = (warp >> 2) * 64, wn = (warp & 3) * 32;

    float acc[4][4][4];
#pragma unroll
    for (int mt = 0; mt < 4; ++mt)
#pragma unroll
        for (int nt = 0; nt < 4; ++nt)
#pragma unroll
            for (int i = 0; i < 4; ++i) acc[mt][nt][i] = 0.f;

    const int srow = t >> 2, sc = t & 3;     // staging: 2 iters cover 128 rows x 4 chunks
    // prologue: stage panel 0
#pragma unroll
    for (int i = 0; i < 2; ++i) {
        int row = srow + i * 64;
        cp16(&Xs[0][row * 40 + sc * 8], X + (size_t)(m0 + row) * 256 + sc * 8);
        cp16(&Ws[0][row * 40 + sc * 8], W + (size_t)(n0 + row) * 256 + sc * 8);
    }
    CP_COMMIT();

    for (int p = 0; p < 8; ++p) {
        CP_WAIT0();
        __syncthreads();
        if (p < 7) {
            int k0 = (p + 1) * 32, buf = (p + 1) & 1;
#pragma unroll
            for (int i = 0; i < 2; ++i) {
                int row = srow + i * 64;
                cp16(&Xs[buf][row * 40 + sc * 8], X + (size_t)(m0 + row) * 256 + k0 + sc * 8);
                cp16(&Ws[buf][row * 40 + sc * 8], W + (size_t)(n0 + row) * 256 + k0 + sc * 8);
            }
        }
        CP_COMMIT();

        const unsigned* Xw = (const unsigned*)Xs[p & 1];
        const unsigned* Ww = (const unsigned*)Ws[p & 1];
#pragma unroll
        for (int kc = 0; kc < 2; ++kc) {
            unsigned a[4][4], bb[4][2];
#pragma unroll
            for (int mt = 0; mt < 4; ++mt) {
                int r = wm + mt * 16 + g;
                a[mt][0] = Xw[r * 20 + 8 * kc + l];
                a[mt][1] = Xw[(r + 8) * 20 + 8 * kc + l];
                a[mt][2] = Xw[r * 20 + 8 * kc + l + 4];
                a[mt][3] = Xw[(r + 8) * 20 + 8 * kc + l + 4];
            }
#pragma unroll
            for (int nt = 0; nt < 4; ++nt) {
                int n = wn + nt * 8 + g;
                bb[nt][0] = Ww[n * 20 + 8 * kc + l];
                bb[nt][1] = Ww[n * 20 + 8 * kc + l + 4];
            }
#pragma unroll
            for (int mt = 0; mt < 4; ++mt)
#pragma unroll
                for (int nt = 0; nt < 4; ++nt)
                    mma_f16(acc[mt][nt], a[mt][0], a[mt][1], a[mt][2], a[mt][3],
                            bb[nt][0], bb[nt][1]);
        }
    }

#pragma unroll
    for (int mt = 0; mt < 4; ++mt) {
#pragma unroll
        for (int nt = 0; nt < 4; ++nt) {
            int r = m0 + wm + mt * 16 + g;
            int c = n0 + wn + nt * 8 + 2 * l;
            if (HALF_OUT) {
                __half* C = (__half*)Cout;
                *(__half2*)(C + (size_t)r * 256 + c)       = __floats2half2_rn(acc[mt][nt][0], acc[mt][nt][1]);
                *(__half2*)(C + (size_t)(r + 8) * 256 + c) = __floats2half2_rn(acc[mt][nt][2], acc[mt][nt][3]);
            } else {
                float* C = (float*)Cout;
                *(float2*)(C + (size_t)r * 256 + c)       = make_float2(acc[mt][nt][0], acc[mt][nt][1]);
                *(float2*)(C + (size_t)(r + 8) * 256 + c) = make_float2(acc[mt][nt][2], acc[mt][nt][3]);
            }
        }
    }
}

// ----------------------------------------------------------------------------
// Attention (fp16): block = 64 queries x one (b,h), 128 threads (4 warps),
// warp owns 16 q-rows. 8 key tiles of 64, cp.async double-buffered.
// P stays in registers (accumulator -> A-fragment direct conversion).
// ----------------------------------------------------------------------------
#define KLDH 40   // K/V row stride halves (80B) -> conflict-free
#define ELDH 72   // em row stride halves (144B) -> conflict-free

__global__ __launch_bounds__(128, 4) void attn_f16(
    const __half* __restrict__ Qh, const __half* __restrict__ Kh,
    const __half* __restrict__ Vh, const __half* __restrict__ em,
    const float* __restrict__ We, __half* __restrict__ AOh)
{
    __shared__ __half Ks[2][64 * KLDH];
    __shared__ __half Vs[2][64 * KLDH];
    __shared__ __half Es[2][64 * ELDH];

    const int t = threadIdx.x, warp = t >> 5, lane = t & 31;
    const int g = lane >> 2, l = lane & 3;
    const int bh = blockIdx.y;
    const int b  = bh >> 3, hh = bh & 7;
    const int q0 = blockIdx.x * 64;
    const size_t bN = (size_t)b * NSEQ;
    const int R0 = warp * 16 + g;            // my fragment row (block-local)
    const float LOG2E = 1.4426950408889634f;
    const float scale = 0.17677669529663687f * LOG2E;  // (1/sqrt(32)) * log2(e)
    const float we    = We[hh] * LOG2E;

    // ---- stage Q (64x32) into Ks[0], extract A-fragments to registers
    {
        int row = t >> 1, c = t & 1;         // 64 rows x 2 chunks of 16 halves? -> use 4 chunks
    }
#pragma unroll
    for (int i = 0; i < 2; ++i) {
        int idx = t + i * 128;               // 0..255 : row = idx>>2 (64), c = idx&3
        int row = idx >> 2, c = idx & 3;
        uint4 v = *(const uint4*)(Qh + ((bN + q0 + row) * DMODEL) + hh * HDIM + c * 8);
        *(uint4*)&Ks[0][row * KLDH + c * 8] = v;
    }
    __syncthreads();

    unsigned qa[2][4];
    {
        const unsigned* Qw = (const unsigned*)Ks[0];
#pragma unroll
        for (int kc = 0; kc < 2; ++kc) {
            qa[kc][0] = Qw[R0 * 20 + 8 * kc + l];
            qa[kc][1] = Qw[(R0 + 8) * 20 + 8 * kc + l];
            qa[kc][2] = Qw[R0 * 20 + 8 * kc + l + 4];
            qa[kc][3] = Qw[(R0 + 8) * 20 + 8 * kc + l + 4];
        }
    }
    __syncthreads();

    float m0r = -1e30f, m1r = -1e30f, l0r = 0.f, l1r = 0.f;
    float o[4][4];
#pragma unroll
    for (int nt = 0; nt < 4; ++nt)
#pragma unroll
        for (int i = 0; i < 4; ++i) o[nt][i] = 0.f;

    // staging index precompute
    const int kv_row = t >> 2, kv_c = t & 3;     // x2 iters: 64 rows x 4 chunks
    const int em_row = t >> 3, em_c = t & 7;     // x4 iters: 64 rows x 8 chunks

    // prologue: stage tile 0
#pragma unroll
    for (int i = 0; i < 2; ++i) {
        int row = kv_row + i * 32;
        const __half* kp = Kh + (bN + row) * DMODEL + hh * HDIM + kv_c * 8;
        const __half* vp = Vh + (bN + row) * DMODEL + hh * HDIM + kv_c * 8;
        cp16(&Ks[0][row * KLDH + kv_c * 8], kp);
        cp16(&Vs[0][row * KLDH + kv_c * 8], vp);
    }
#pragma unroll
    for (int i = 0; i < 4; ++i) {
        int row = em_row + i * 16;
        cp16(&Es[0][row * ELDH + em_c * 8],
             em + ((bN + q0 + row) * NSEQ) + em_c * 8);
    }
    CP_COMMIT();

    for (int it = 0; it < 8; ++it) {
        CP_WAIT0();
        __syncthreads();
        if (it < 7) {
            int jt = (it + 1) * 64, buf = (it + 1) & 1;
#pragma unroll
            for (int i = 0; i < 2; ++i) {
                int row = kv_row + i * 32;
                cp16(&Ks[buf][row * KLDH + kv_c * 8],
                     Kh + (bN + jt + row) * DMODEL + hh * HDIM + kv_c * 8);
                cp16(&Vs[buf][row * KLDH + kv_c * 8],
                     Vh + (bN + jt + row) * DMODEL + hh * HDIM + kv_c * 8);
            }
#pragma unroll
            for (int i = 0; i < 4; ++i) {
                int row = em_row + i * 16;
                cp16(&Es[buf][row * ELDH + em_c * 8],
                     em + ((bN + q0 + row) * NSEQ) + jt + em_c * 8);
            }
        }
        CP_COMMIT();

        const unsigned* Kw = (const unsigned*)Ks[it & 1];
        const unsigned* Ew = (const unsigned*)Es[it & 1];
        const __half*   Vb = Vs[it & 1];

        // ---- S = Q K^T : 16 q-rows x 64 keys
        float s[8][4];
#pragma unroll
        for (int nt = 0; nt < 8; ++nt)
#pragma unroll
            for (int i = 0; i < 4; ++i) s[nt][i] = 0.f;

#pragma unroll
        for (int kc = 0; kc < 2; ++kc)
#pragma unroll
            for (int nt = 0; nt < 8; ++nt) {
                unsigned b0 = Kw[(8 * nt + g) * 20 + 8 * kc + l];
                unsigned b1 = Kw[(8 * nt + g) * 20 + 8 * kc + l + 4];
                mma_f16(s[nt], qa[kc][0], qa[kc][1], qa[kc][2], qa[kc][3], b0, b1);
            }

        // ---- bias + mask(NaN) + online softmax (log2 domain)
        float mn0 = m0r, mn1 = m1r;
#pragma unroll
        for (int nt = 0; nt < 8; ++nt) {
            unsigned w01 = Ew[R0 * 36 + 4 * nt + l];
            unsigned w23 = Ew[(R0 + 8) * 36 + 4 * nt + l];
            float2 e01 = __half22float2(*(__half2*)&w01);
            float2 e23 = __half22float2(*(__half2*)&w23);
            s[nt][0] = fmaxf(fmaf(we, e01.x, s[nt][0] * scale), -1e30f);
            s[nt][1] = fmaxf(fmaf(we, e01.y, s[nt][1] * scale), -1e30f);
            s[nt][2] = fmaxf(fmaf(we, e23.x, s[nt][2] * scale), -1e30f);
            s[nt][3] = fmaxf(fmaf(we, e23.y, s[nt][3] * scale), -1e30f);
            mn0 = fmaxf(mn0, fmaxf(s[nt][0], s[nt][1]));
            mn1 = fmaxf(mn1, fmaxf(s[nt][2], s[nt][3]));
        }
        mn0 = fmaxf(mn0, __shfl_xor_sync(0xffffffff, mn0, 1));
        mn0 = fmaxf(mn0, __shfl_xor_sync(0xffffffff, mn0, 2));
        mn1 = fmaxf(mn1, __shfl_xor_sync(0xffffffff, mn1, 1));
        mn1 = fmaxf(mn1, __shfl_xor_sync(0xffffffff, mn1, 2));

        float corr0 = exp2f(m0r - mn0);
        float corr1 = exp2f(m1r - mn1);
        m0r = mn0; m1r = mn1;

        float ps0 = 0.f, ps1 = 0.f;
#pragma unroll
        for (int nt = 0; nt < 8; ++nt) {
            s[nt][0] = exp2f(s[nt][0] - mn0);
            s[nt][1] = exp2f(s[nt][1] - mn0);
            s[nt][2] = exp2f(s[nt][2] - mn1);
            s[nt][3] = exp2f(s[nt][3] - mn1);
            ps0 += s[nt][0] + s[nt][1];
            ps1 += s[nt][2] + s[nt][3];
        }
        ps0 += __shfl_xor_sync(0xffffffff, ps0, 1);
        ps0 += __shfl_xor_sync(0xffffffff, ps0, 2);
        ps1 += __shfl_xor_sync(0xffffffff, ps1, 1);
        ps1 += __shfl_xor_sync(0xffffffff, ps1, 2);
        l0r = l0r * corr0 + ps0;
        l1r = l1r * corr1 + ps1;

#pragma unroll
        for (int nt = 0; nt < 4; ++nt) {
            o[nt][0] *= corr0; o[nt][1] *= corr0;
            o[nt][2] *= corr1; o[nt][3] *= corr1;
        }

        // ---- O += P @ V : P fragments built in registers from s[][]
        const int vkey = ((lane >> 3) & 1) << 3;        // +8 keys for m1/m3
        const int vd   = ((lane >> 4) & 1) << 3;        // +8 d-cols for m2/m3
        const int vr   = lane & 7;
#pragma unroll
        for (int kc = 0; kc < 4; ++kc) {
            unsigned a0 = f2h2(s[2 * kc][0],     s[2 * kc][1]);
            unsigned a1 = f2h2(s[2 * kc][2],     s[2 * kc][3]);
            unsigned a2 = f2h2(s[2 * kc + 1][0], s[2 * kc + 1][1]);
            unsigned a3 = f2h2(s[2 * kc + 1][2], s[2 * kc + 1][3]);
            unsigned v0, v1, v2, v3, v4, v5, v6, v7;
            const __half* base = Vb + (16 * kc + vkey + vr) * KLDH + vd;
            ldsm4t(v0, v1, v2, v3, base);        // d cols [0,16)  -> nt 0,1
            ldsm4t(v4, v5, v6, v7, base + 16);   // d cols [16,32) -> nt 2,3
            mma_f16(o[0], a0, a1, a2, a3, v0, v1);
            mma_f16(o[1], a0, a1, a2, a3, v2, v3);
            mma_f16(o[2], a0, a1, a2, a3, v4, v5);
            mma_f16(o[3], a0, a1, a2, a3, v6, v7);
        }
    }

    // ---- write output (fp16)
    const float inv0 = 1.0f / l0r;
    const float inv1 = 1.0f / l1r;
#pragma unroll
    for (int nt = 0; nt < 4; ++nt) {
        int c = hh * HDIM + nt * 8 + 2 * l;
        *(__half2*)(AOh + (bN + q0 + R0) * DMODEL + c) =
            __floats2half2_rn(o[nt][0] * inv0, o[nt][1] * inv0);
        *(__half2*)(AOh + (bN + q0 + R0 + 8) * DMODEL + c) =
            __floats2half2_rn(o[nt][2] * inv1, o[nt][3] * inv1);
    }
}

// ----------------------------------------------------------------------------
// launch
// ----------------------------------------------------------------------------
extern "C" void kernel_launch(void* const* d_in, const int* in_sizes, int n_in,
                              void* d_out, int out_size)
{
    const float* h    = (const float*)d_in[0];
    const float* edge = (const float*)d_in[1];
    const int*   mask = (const int*)  d_in[2];
    const float* Wq   = (const float*)d_in[3];
    const float* Wk   = (const float*)d_in[4];
    const float* Wv   = (const float*)d_in[5];
    const float* We   = (const float*)d_in[6];
    const float* Wo   = (const float*)d_in[7];
    float* out = (float*)d_out;

    __half *h16, *q16, *k16, *v16, *ao16, *emh, *w16;
    cudaGetSymbolAddress((void**)&h16,  g_h16);
    cudaGetSymbolAddress((void**)&q16,  g_q16);
    cudaGetSymbolAddress((void**)&k16,  g_k16);
    cudaGetSymbolAddress((void**)&v16,  g_v16);
    cudaGetSymbolAddress((void**)&ao16, g_ao16);
    cudaGetSymbolAddress((void**)&emh,  g_em);
    cudaGetSymbolAddress((void**)&w16,  g_w16);

    // preprocess: fp32 -> fp16 (h, 4x W), edge+mask -> em
    prep_f2h<<<(MROWS * DMODEL / 4 + 255) / 256, 256>>>(h, h16, MROWS * DMODEL / 4);
    prep_f2h<<<(DMODEL * DMODEL / 4 + 255) / 256, 256>>>(Wq, w16 + 0 * DMODEL * DMODEL, DMODEL * DMODEL / 4);
    prep_f2h<<<(DMODEL * DMODEL / 4 + 255) / 256, 256>>>(Wk, w16 + 1 * DMODEL * DMODEL, DMODEL * DMODEL / 4);
    prep_f2h<<<(DMODEL * DMODEL / 4 + 255) / 256, 256>>>(Wv, w16 + 2 * DMODEL * DMODEL, DMODEL * DMODEL / 4);
    prep_f2h<<<(DMODEL * DMODEL / 4 + 255) / 256, 256>>>(Wo, w16 + 3 * DMODEL * DMODEL, DMODEL * DMODEL / 4);
    prep_em<<<(BATCH * NSEQ * NSEQ / 4 + 255) / 256, 256>>>(edge, mask, emh, BATCH * NSEQ * NSEQ / 4);

    dim3 pgrid(DMODEL / 128, MROWS / 128);   // (2, 128)
    gemm_f16<true><<<pgrid, 256>>>(h16, w16 + 0 * DMODEL * DMODEL, q16);
    gemm_f16<true><<<pgrid, 256>>>(h16, w16 + 1 * DMODEL * DMODEL, k16);
    gemm_f16<true><<<pgrid, 256>>>(h16, w16 + 2 * DMODEL * DMODEL, v16);

    attn_f16<<<dim3(NSEQ / 64, BATCH * NHEAD), 128>>>(q16, k16, v16, emh, We, ao16);

    gemm_f16<false><<<pgrid, 256>>>(ao16, w16 + 3 * DMODEL * DMODEL, out);
}

// round 6
// speedup vs baseline: 2.0466x; 1.1385x over previous
#include <cuda_runtime.h>
#include <cuda_fp16.h>
#include <math.h>

// ----------------------------------------------------------------------------
// EdgeBiasedAttention — fp16 mma.m16n8k16 pipeline (v6)
// B=32, N=512, D=256, H=8, HD=32
// v6: single fused prep kernel, fused QKV GEMM (scale folded into Q),
//     half2 ex2 softmax epilogue producing PV fragments directly.
// ----------------------------------------------------------------------------

#define BATCH 32
#define NSEQ  512
#define DMODEL 256
#define NHEAD 8
#define HDIM  32
#define MROWS (BATCH * NSEQ)  // 16384

#define N_H4 (MROWS * DMODEL / 4)          // 1048576
#define N_W4 (DMODEL * DMODEL / 4)         // 16384
#define N_E4 (BATCH * NSEQ * NSEQ / 4)     // 2097152
#define N_TOT4 (N_H4 + 4 * N_W4 + N_E4)    // 3211264

// fp16 scratch
__device__ __half g_h16 [MROWS * DMODEL];
__device__ __half g_q16 [MROWS * DMODEL];
__device__ __half g_k16 [MROWS * DMODEL];
__device__ __half g_v16 [MROWS * DMODEL];
__device__ __half g_ao16[MROWS * DMODEL];
__device__ __half g_em  [BATCH * NSEQ * NSEQ];   // masked edge (NaN = masked)
__device__ __half g_w16 [4 * DMODEL * DMODEL];   // Wq, Wk, Wv, Wo fp16

// ---------------- helpers ----------------
__device__ __forceinline__ void mma_f16(float c[4],
                                        unsigned a0, unsigned a1, unsigned a2, unsigned a3,
                                        unsigned b0, unsigned b1)
{
    asm volatile(
        "mma.sync.aligned.m16n8k16.row.col.f32.f16.f16.f32 "
        "{%0,%1,%2,%3}, {%4,%5,%6,%7}, {%8,%9}, {%0,%1,%2,%3};"
        : "+f"(c[0]), "+f"(c[1]), "+f"(c[2]), "+f"(c[3])
        : "r"(a0), "r"(a1), "r"(a2), "r"(a3), "r"(b0), "r"(b1));
}

__device__ __forceinline__ void cp16(void* sdst, const void* gsrc) {
    unsigned s = (unsigned)__cvta_generic_to_shared(sdst);
    asm volatile("cp.async.cg.shared.global [%0], [%1], 16;" :: "r"(s), "l"(gsrc));
}
#define CP_COMMIT() asm volatile("cp.async.commit_group;")
#define CP_WAIT0()  asm volatile("cp.async.wait_group 0;" ::: "memory")

__device__ __forceinline__ void ldsm4t(unsigned& r0, unsigned& r1, unsigned& r2, unsigned& r3,
                                       const __half* p)
{
    unsigned s = (unsigned)__cvta_generic_to_shared(p);
    asm volatile("ldmatrix.sync.aligned.m8n8.x4.trans.shared.b16 {%0,%1,%2,%3}, [%4];"
                 : "=r"(r0), "=r"(r1), "=r"(r2), "=r"(r3) : "r"(s));
}

// ---------------- fused preprocessing (one launch) ----------------
__global__ __launch_bounds__(256) void prep_all(
    const float* __restrict__ h,
    const float* __restrict__ Wq, const float* __restrict__ Wk,
    const float* __restrict__ Wv, const float* __restrict__ Wo,
    const float* __restrict__ edge, const int* __restrict__ mask,
    __half* __restrict__ h16, __half* __restrict__ w16, __half* __restrict__ em)
{
    int i = blockIdx.x * 256 + threadIdx.x;
    if (i < N_H4) {
        float4 v = ((const float4*)h)[i];
        __half2* d = (__half2*)h16 + (size_t)i * 2;
        d[0] = __floats2half2_rn(v.x, v.y);
        d[1] = __floats2half2_rn(v.z, v.w);
    } else if (i < N_H4 + 4 * N_W4) {
        int j = i - N_H4;
        int which = j >> 14, off = j & (N_W4 - 1);
        const float* W = which == 0 ? Wq : which == 1 ? Wk : which == 2 ? Wv : Wo;
        float4 v = ((const float4*)W)[off];
        __half2* d = (__half2*)w16 + ((size_t)which * N_W4 + off) * 2;
        d[0] = __floats2half2_rn(v.x, v.y);
        d[1] = __floats2half2_rn(v.z, v.w);
    } else if (i < N_TOT4) {
        const float QNAN = __int_as_float(0x7fc00000);
        int j = i - (N_H4 + 4 * N_W4);
        float4 e = ((const float4*)edge)[j];
        int4   m = ((const int4*)mask)[j];
        __half2* d = (__half2*)em + (size_t)j * 2;
        d[0] = __floats2half2_rn(m.x ? e.x : QNAN, m.y ? e.y : QNAN);
        d[1] = __floats2half2_rn(m.z ? e.z : QNAN, m.w ? e.w : QNAN);
    }
}

// ----------------------------------------------------------------------------
// Fused QKV GEMM: [Q|K|V][M,256] = X[M,256] @ Wcat[768,256]^T (fp16 out).
// grid (6,128); bx>>1 selects destination; Q output pre-scaled by
// (1/sqrt(32))*log2(e). Block 128x128, BK=32, cp.async double-buffered.
// ----------------------------------------------------------------------------
__global__ __launch_bounds__(256, 2) void gemm_qkv(const __half* __restrict__ X,
                                                   const __half* __restrict__ Wcat,
                                                   __half* __restrict__ Qd,
                                                   __half* __restrict__ Kd,
                                                   __half* __restrict__ Vd)
{
    __shared__ __half Xs[2][128 * 40];
    __shared__ __half Ws[2][128 * 40];

    const int t = threadIdx.x, warp = t >> 5, lane = t & 31;
    const int g = lane >> 2, l = lane & 3;
    const int m0 = blockIdx.y * 128, n0 = blockIdx.x * 128;
    const int wm = (warp >> 2) * 64, wn = (warp & 3) * 32;
    const int which = blockIdx.x >> 1;
    __half* dst = which == 0 ? Qd : which == 1 ? Kd : Vd;
    const int nloc = n0 & 255;
    const float oscale = (which == 0) ? 0.17677669529663687f * 1.4426950408889634f : 1.0f;

    float acc[4][4][4];
#pragma unroll
    for (int mt = 0; mt < 4; ++mt)
#pragma unroll
        for (int nt = 0; nt < 4; ++nt)
#pragma unroll
            for (int i = 0; i < 4; ++i) acc[mt][nt][i] = 0.f;

    const int srow = t >> 2, sc = t & 3;
#pragma unroll
    for (int i = 0; i < 2; ++i) {
        int row = srow + i * 64;
        cp16(&Xs[0][row * 40 + sc * 8], X + (size_t)(m0 + row) * 256 + sc * 8);
        cp16(&Ws[0][row * 40 + sc * 8], Wcat + (size_t)(n0 + row) * 256 + sc * 8);
    }
    CP_COMMIT();

    for (int p = 0; p < 8; ++p) {
        CP_WAIT0();
        __syncthreads();
        if (p < 7) {
            int k0 = (p + 1) * 32, buf = (p + 1) & 1;
#pragma unroll
            for (int i = 0; i < 2; ++i) {
                int row = srow + i * 64;
                cp16(&Xs[buf][row * 40 + sc * 8], X + (size_t)(m0 + row) * 256 + k0 + sc * 8);
                cp16(&Ws[buf][row * 40 + sc * 8], Wcat + (size_t)(n0 + row) * 256 + k0 + sc * 8);
            }
        }
        CP_COMMIT();

        const unsigned* Xw = (const unsigned*)Xs[p & 1];
        const unsigned* Ww = (const unsigned*)Ws[p & 1];
#pragma unroll
        for (int kc = 0; kc < 2; ++kc) {
            unsigned a[4][4], bb[4][2];
#pragma unroll
            for (int mt = 0; mt < 4; ++mt) {
                int r = wm + mt * 16 + g;
                a[mt][0] = Xw[r * 20 + 8 * kc + l];
                a[mt][1] = Xw[(r + 8) * 20 + 8 * kc + l];
                a[mt][2] = Xw[r * 20 + 8 * kc + l + 4];
                a[mt][3] = Xw[(r + 8) * 20 + 8 * kc + l + 4];
            }
#pragma unroll
            for (int nt = 0; nt < 4; ++nt) {
                int n = wn + nt * 8 + g;
                bb[nt][0] = Ww[n * 20 + 8 * kc + l];
                bb[nt][1] = Ww[n * 20 + 8 * kc + l + 4];
            }
#pragma unroll
            for (int mt = 0; mt < 4; ++mt)
#pragma unroll
                for (int nt = 0; nt < 4; ++nt)
                    mma_f16(acc[mt][nt], a[mt][0], a[mt][1], a[mt][2], a[mt][3],
                            bb[nt][0], bb[nt][1]);
        }
    }

#pragma unroll
    for (int mt = 0; mt < 4; ++mt) {
#pragma unroll
        for (int nt = 0; nt < 4; ++nt) {
            int r = m0 + wm + mt * 16 + g;
            int c = nloc + wn + nt * 8 + 2 * l;
            *(__half2*)(dst + (size_t)r * 256 + c) =
                __floats2half2_rn(acc[mt][nt][0] * oscale, acc[mt][nt][1] * oscale);
            *(__half2*)(dst + (size_t)(r + 8) * 256 + c) =
                __floats2half2_rn(acc[mt][nt][2] * oscale, acc[mt][nt][3] * oscale);
        }
    }
}

// ----------------------------------------------------------------------------
// Output GEMM: out[M,256] (fp32) = AO[M,256] @ Wo[256,256]^T
// ----------------------------------------------------------------------------
__global__ __launch_bounds__(256, 2) void gemm_out(const __half* __restrict__ X,
                                                   const __half* __restrict__ W,
                                                   float* __restrict__ C)
{
    __shared__ __half Xs[2][128 * 40];
    __shared__ __half Ws[2][128 * 40];

    const int t = threadIdx.x, warp = t >> 5, lane = t & 31;
    const int g = lane >> 2, l = lane & 3;
    const int m0 = blockIdx.y * 128, n0 = blockIdx.x * 128;
    const int wm = (warp >> 2) * 64, wn = (warp & 3) * 32;

    float acc[4][4][4];
#pragma unroll
    for (int mt = 0; mt < 4; ++mt)
#pragma unroll
        for (int nt = 0; nt < 4; ++nt)
#pragma unroll
            for (int i = 0; i < 4; ++i) acc[mt][nt][i] = 0.f;

    const int srow = t >> 2, sc = t & 3;
#pragma unroll
    for (int i = 0; i < 2; ++i) {
        int row = srow + i * 64;
        cp16(&Xs[0][row * 40 + sc * 8], X + (size_t)(m0 + row) * 256 + sc * 8);
        cp16(&Ws[0][row * 40 + sc * 8], W + (size_t)(n0 + row) * 256 + sc * 8);
    }
    CP_COMMIT();

    for (int p = 0; p < 8; ++p) {
        CP_WAIT0();
        __syncthreads();
        if (p < 7) {
            int k0 = (p + 1) * 32, buf = (p + 1) & 1;
#pragma unroll
            for (int i = 0; i < 2; ++i) {
                int row = srow + i * 64;
                cp16(&Xs[buf][row * 40 + sc * 8], X + (size_t)(m0 + row) * 256 + k0 + sc * 8);
                cp16(&Ws[buf][row * 40 + sc * 8], W + (size_t)(n0 + row) * 256 + k0 + sc * 8);
            }
        }
        CP_COMMIT();

        const unsigned* Xw = (const unsigned*)Xs[p & 1];
        const unsigned* Ww = (const unsigned*)Ws[p & 1];
#pragma unroll
        for (int kc = 0; kc < 2; ++kc) {
            unsigned a[4][4], bb[4][2];
#pragma unroll
            for (int mt = 0; mt < 4; ++mt) {
                int r = wm + mt * 16 + g;
                a[mt][0] = Xw[r * 20 + 8 * kc + l];
                a[mt][1] = Xw[(r + 8) * 20 + 8 * kc + l];
                a[mt][2] = Xw[r * 20 + 8 * kc + l + 4];
                a[mt][3] = Xw[(r + 8) * 20 + 8 * kc + l + 4];
            }
#pragma unroll
            for (int nt = 0; nt < 4; ++nt) {
                int n = wn + nt * 8 + g;
                bb[nt][0] = Ww[n * 20 + 8 * kc + l];
                bb[nt][1] = Ww[n * 20 + 8 * kc + l + 4];
            }
#pragma unroll
            for (int mt = 0; mt < 4; ++mt)
#pragma unroll
                for (int nt = 0; nt < 4; ++nt)
                    mma_f16(acc[mt][nt], a[mt][0], a[mt][1], a[mt][2], a[mt][3],
                            bb[nt][0], bb[nt][1]);
        }
    }

#pragma unroll
    for (int mt = 0; mt < 4; ++mt) {
#pragma unroll
        for (int nt = 0; nt < 4; ++nt) {
            int r = m0 + wm + mt * 16 + g;
            int c = n0 + wn + nt * 8 + 2 * l;
            *(float2*)(C + (size_t)r * 256 + c)       = make_float2(acc[mt][nt][0], acc[mt][nt][1]);
            *(float2*)(C + (size_t)(r + 8) * 256 + c) = make_float2(acc[mt][nt][2], acc[mt][nt][3]);
        }
    }
}

// ----------------------------------------------------------------------------
// Attention (fp16): block = 64 queries x one (b,h), 128 threads (4 warps).
// Q pre-scaled in GEMM; softmax in log2 domain; p via ex2.approx.f16x2,
// producing PV A-fragments directly.
// ----------------------------------------------------------------------------
#define KLDH 40   // K/V row stride halves (80B) -> conflict-free
#define ELDH 72   // em row stride halves (144B) -> conflict-free

__global__ __launch_bounds__(128, 4) void attn_f16(
    const __half* __restrict__ Qh, const __half* __restrict__ Kh,
    const __half* __restrict__ Vh, const __half* __restrict__ em,
    const float* __restrict__ We, __half* __restrict__ AOh)
{
    __shared__ __half Ks[2][64 * KLDH];
    __shared__ __half Vs[2][64 * KLDH];
    __shared__ __half Es[2][64 * ELDH];

    const int t = threadIdx.x, warp = t >> 5, lane = t & 31;
    const int g = lane >> 2, l = lane & 3;
    const int bh = blockIdx.y;
    const int b  = bh >> 3, hh = bh & 7;
    const int q0 = blockIdx.x * 64;
    const size_t bN = (size_t)b * NSEQ;
    const int R0 = warp * 16 + g;
    const float we = We[hh] * 1.4426950408889634f;   // log2 domain

    // ---- stage Q (64x32, already scaled) into Ks[0], fragments to registers
#pragma unroll
    for (int i = 0; i < 2; ++i) {
        int idx = t + i * 128;
        int row = idx >> 2, c = idx & 3;
        uint4 v = *(const uint4*)(Qh + ((bN + q0 + row) * DMODEL) + hh * HDIM + c * 8);
        *(uint4*)&Ks[0][row * KLDH + c * 8] = v;
    }
    __syncthreads();

    unsigned qa[2][4];
    {
        const unsigned* Qw = (const unsigned*)Ks[0];
#pragma unroll
        for (int kc = 0; kc < 2; ++kc) {
            qa[kc][0] = Qw[R0 * 20 + 8 * kc + l];
            qa[kc][1] = Qw[(R0 + 8) * 20 + 8 * kc + l];
            qa[kc][2] = Qw[R0 * 20 + 8 * kc + l + 4];
            qa[kc][3] = Qw[(R0 + 8) * 20 + 8 * kc + l + 4];
        }
    }
    __syncthreads();

    float m0r = -1e30f, m1r = -1e30f, l0r = 0.f, l1r = 0.f;
    float o[4][4];
#pragma unroll
    for (int nt = 0; nt < 4; ++nt)
#pragma unroll
        for (int i = 0; i < 4; ++i) o[nt][i] = 0.f;

    const int kv_row = t >> 2, kv_c = t & 3;
    const int em_row = t >> 3, em_c = t & 7;

#pragma unroll
    for (int i = 0; i < 2; ++i) {
        int row = kv_row + i * 32;
        cp16(&Ks[0][row * KLDH + kv_c * 8], Kh + (bN + row) * DMODEL + hh * HDIM + kv_c * 8);
        cp16(&Vs[0][row * KLDH + kv_c * 8], Vh + (bN + row) * DMODEL + hh * HDIM + kv_c * 8);
    }
#pragma unroll
    for (int i = 0; i < 4; ++i) {
        int row = em_row + i * 16;
        cp16(&Es[0][row * ELDH + em_c * 8], em + ((bN + q0 + row) * NSEQ) + em_c * 8);
    }
    CP_COMMIT();

    for (int it = 0; it < 8; ++it) {
        CP_WAIT0();
        __syncthreads();
        if (it < 7) {
            int jt = (it + 1) * 64, buf = (it + 1) & 1;
#pragma unroll
            for (int i = 0; i < 2; ++i) {
                int row = kv_row + i * 32;
                cp16(&Ks[buf][row * KLDH + kv_c * 8],
                     Kh + (bN + jt + row) * DMODEL + hh * HDIM + kv_c * 8);
                cp16(&Vs[buf][row * KLDH + kv_c * 8],
                     Vh + (bN + jt + row) * DMODEL + hh * HDIM + kv_c * 8);
            }
#pragma unroll
            for (int i = 0; i < 4; ++i) {
                int row = em_row + i * 16;
                cp16(&Es[buf][row * ELDH + em_c * 8],
                     em + ((bN + q0 + row) * NSEQ) + jt + em_c * 8);
            }
        }
        CP_COMMIT();

        const unsigned* Kw = (const unsigned*)Ks[it & 1];
        const unsigned* Ew = (const unsigned*)Es[it & 1];
        const __half*   Vb = Vs[it & 1];

        // ---- S = Q K^T (Q pre-scaled): 16 q-rows x 64 keys
        float s[8][4];
#pragma unroll
        for (int nt = 0; nt < 8; ++nt)
#pragma unroll
            for (int i = 0; i < 4; ++i) s[nt][i] = 0.f;

#pragma unroll
        for (int kc = 0; kc < 2; ++kc)
#pragma unroll
            for (int nt = 0; nt < 8; ++nt) {
                unsigned b0 = Kw[(8 * nt + g) * 20 + 8 * kc + l];
                unsigned b1 = Kw[(8 * nt + g) * 20 + 8 * kc + l + 4];
                mma_f16(s[nt], qa[kc][0], qa[kc][1], qa[kc][2], qa[kc][3], b0, b1);
            }

        // ---- bias + mask(NaN) + online max (fp32, log2 domain)
        float mn0 = m0r, mn1 = m1r;
#pragma unroll
        for (int nt = 0; nt < 8; ++nt) {
            unsigned w01 = Ew[R0 * 36 + 4 * nt + l];
            unsigned w23 = Ew[(R0 + 8) * 36 + 4 * nt + l];
            float2 e01 = __half22float2(*(__half2*)&w01);
            float2 e23 = __half22float2(*(__half2*)&w23);
            s[nt][0] = fmaxf(fmaf(we, e01.x, s[nt][0]), -1e30f);
            s[nt][1] = fmaxf(fmaf(we, e01.y, s[nt][1]), -1e30f);
            s[nt][2] = fmaxf(fmaf(we, e23.x, s[nt][2]), -1e30f);
            s[nt][3] = fmaxf(fmaf(we, e23.y, s[nt][3]), -1e30f);
            mn0 = fmaxf(mn0, fmaxf(s[nt][0], s[nt][1]));
            mn1 = fmaxf(mn1, fmaxf(s[nt][2], s[nt][3]));
        }
        mn0 = fmaxf(mn0, __shfl_xor_sync(0xffffffff, mn0, 1));
        mn0 = fmaxf(mn0, __shfl_xor_sync(0xffffffff, mn0, 2));
        mn1 = fmaxf(mn1, __shfl_xor_sync(0xffffffff, mn1, 1));
        mn1 = fmaxf(mn1, __shfl_xor_sync(0xffffffff, mn1, 2));

        float corr0 = exp2f(m0r - mn0);
        float corr1 = exp2f(m1r - mn1);
        m0r = mn0; m1r = mn1;

        // ---- p = ex2.f16x2(s - mn): directly the PV A-fragments
        unsigned ph[8][2];
        float ps0 = 0.f, ps1 = 0.f;
#pragma unroll
        for (int nt = 0; nt < 8; ++nt) {
            __half2 x01 = __floats2half2_rn(s[nt][0] - mn0, s[nt][1] - mn0);
            __half2 x23 = __floats2half2_rn(s[nt][2] - mn1, s[nt][3] - mn1);
            __half2 p01 = h2exp2(x01);
            __half2 p23 = h2exp2(x23);
            ph[nt][0] = *(unsigned*)&p01;
            ph[nt][1] = *(unsigned*)&p23;
            float2 f01 = __half22float2(p01);
            float2 f23 = __half22float2(p23);
            ps0 += f01.x + f01.y;
            ps1 += f23.x + f23.y;
        }
        ps0 += __shfl_xor_sync(0xffffffff, ps0, 1);
        ps0 += __shfl_xor_sync(0xffffffff, ps0, 2);
        ps1 += __shfl_xor_sync(0xffffffff, ps1, 1);
        ps1 += __shfl_xor_sync(0xffffffff, ps1, 2);
        l0r = l0r * corr0 + ps0;
        l1r = l1r * corr1 + ps1;

#pragma unroll
        for (int nt = 0; nt < 4; ++nt) {
            o[nt][0] *= corr0; o[nt][1] *= corr0;
            o[nt][2] *= corr1; o[nt][3] *= corr1;
        }

        // ---- O += P @ V
        const int vkey = ((lane >> 3) & 1) << 3;
        const int vd   = ((lane >> 4) & 1) << 3;
        const int vr   = lane & 7;
#pragma unroll
        for (int kc = 0; kc < 4; ++kc) {
            unsigned a0 = ph[2 * kc][0];
            unsigned a1 = ph[2 * kc][1];
            unsigned a2 = ph[2 * kc + 1][0];
            unsigned a3 = ph[2 * kc + 1][1];
            unsigned v0, v1, v2, v3, v4, v5, v6, v7;
            const __half* base = Vb + (16 * kc + vkey + vr) * KLDH + vd;
            ldsm4t(v0, v1, v2, v3, base);
            ldsm4t(v4, v5, v6, v7, base + 16);
            mma_f16(o[0], a0, a1, a2, a3, v0, v1);
            mma_f16(o[1], a0, a1, a2, a3, v2, v3);
            mma_f16(o[2], a0, a1, a2, a3, v4, v5);
            mma_f16(o[3], a0, a1, a2, a3, v6, v7);
        }
    }

    // ---- write output (fp16)
    const float inv0 = 1.0f / l0r;
    const float inv1 = 1.0f / l1r;
#pragma unroll
    for (int nt = 0; nt < 4; ++nt) {
        int c = hh * HDIM + nt * 8 + 2 * l;
        *(__half2*)(AOh + (bN + q0 + R0) * DMODEL + c) =
            __floats2half2_rn(o[nt][0] * inv0, o[nt][1] * inv0);
        *(__half2*)(AOh + (bN + q0 + R0 + 8) * DMODEL + c) =
            __floats2half2_rn(o[nt][2] * inv1, o[nt][3] * inv1);
    }
}

// ----------------------------------------------------------------------------
// launch
// ----------------------------------------------------------------------------
extern "C" void kernel_launch(void* const* d_in, const int* in_sizes, int n_in,
                              void* d_out, int out_size)
{
    const float* h    = (const float*)d_in[0];
    const float* edge = (const float*)d_in[1];
    const int*   mask = (const int*)  d_in[2];
    const float* Wq   = (const float*)d_in[3];
    const float* Wk   = (const float*)d_in[4];
    const float* Wv   = (const float*)d_in[5];
    const float* We   = (const float*)d_in[6];
    const float* Wo   = (const float*)d_in[7];
    float* out = (float*)d_out;

    __half *h16, *q16, *k16, *v16, *ao16, *emh, *w16;
    cudaGetSymbolAddress((void**)&h16,  g_h16);
    cudaGetSymbolAddress((void**)&q16,  g_q16);
    cudaGetSymbolAddress((void**)&k16,  g_k16);
    cudaGetSymbolAddress((void**)&v16,  g_v16);
    cudaGetSymbolAddress((void**)&ao16, g_ao16);
    cudaGetSymbolAddress((void**)&emh,  g_em);
    cudaGetSymbolAddress((void**)&w16,  g_w16);

    prep_all<<<N_TOT4 / 256, 256>>>(h, Wq, Wk, Wv, Wo, edge, mask, h16, w16, emh);

    gemm_qkv<<<dim3(6, MROWS / 128), 256>>>(h16, w16, q16, k16, v16);

    attn_f16<<<dim3(NSEQ / 64, BATCH * NHEAD), 128>>>(q16, k16, v16, emh, We, ao16);

    gemm_out<<<dim3(2, MROWS / 128), 256>>>(ao16, w16 + 3 * DMODEL * DMODEL, out);
}

// round 7
// speedup vs baseline: 2.1698x; 1.0602x over previous
#include <cuda_runtime.h>
#include <cuda_fp16.h>
#include <math.h>

// ----------------------------------------------------------------------------
// EdgeBiasedAttention — fp16 mma.m16n8k16 pipeline (v7)
// v7: all fragment loads via ldmatrix.x4 (GEMM A/B, attn K, em bias, Q setup)
// B=32, N=512, D=256, H=8, HD=32
// ----------------------------------------------------------------------------

#define BATCH 32
#define NSEQ  512
#define DMODEL 256
#define NHEAD 8
#define HDIM  32
#define MROWS (BATCH * NSEQ)  // 16384

#define N_H4 (MROWS * DMODEL / 4)          // 1048576
#define N_W4 (DMODEL * DMODEL / 4)         // 16384
#define N_E4 (BATCH * NSEQ * NSEQ / 4)     // 2097152
#define N_TOT4 (N_H4 + 4 * N_W4 + N_E4)    // 3211264

// fp16 scratch
__device__ __half g_h16 [MROWS * DMODEL];
__device__ __half g_q16 [MROWS * DMODEL];
__device__ __half g_k16 [MROWS * DMODEL];
__device__ __half g_v16 [MROWS * DMODEL];
__device__ __half g_ao16[MROWS * DMODEL];
__device__ __half g_em  [BATCH * NSEQ * NSEQ];   // masked edge (NaN = masked)
__device__ __half g_w16 [4 * DMODEL * DMODEL];   // Wq, Wk, Wv, Wo fp16

// ---------------- helpers ----------------
__device__ __forceinline__ void mma_f16(float c[4],
                                        unsigned a0, unsigned a1, unsigned a2, unsigned a3,
                                        unsigned b0, unsigned b1)
{
    asm volatile(
        "mma.sync.aligned.m16n8k16.row.col.f32.f16.f16.f32 "
        "{%0,%1,%2,%3}, {%4,%5,%6,%7}, {%8,%9}, {%0,%1,%2,%3};"
        : "+f"(c[0]), "+f"(c[1]), "+f"(c[2]), "+f"(c[3])
        : "r"(a0), "r"(a1), "r"(a2), "r"(a3), "r"(b0), "r"(b1));
}

__device__ __forceinline__ void cp16(void* sdst, const void* gsrc) {
    unsigned s = (unsigned)__cvta_generic_to_shared(sdst);
    asm volatile("cp.async.cg.shared.global [%0], [%1], 16;" :: "r"(s), "l"(gsrc));
}
#define CP_COMMIT() asm volatile("cp.async.commit_group;")
#define CP_WAIT0()  asm volatile("cp.async.wait_group 0;" ::: "memory")

// ldmatrix non-transposed x4
__device__ __forceinline__ void ldsm4(unsigned& r0, unsigned& r1, unsigned& r2, unsigned& r3,
                                      const __half* p)
{
    unsigned s = (unsigned)__cvta_generic_to_shared(p);
    asm volatile("ldmatrix.sync.aligned.m8n8.x4.shared.b16 {%0,%1,%2,%3}, [%4];"
                 : "=r"(r0), "=r"(r1), "=r"(r2), "=r"(r3) : "r"(s));
}
// ldmatrix transposed x4 (for V)
__device__ __forceinline__ void ldsm4t(unsigned& r0, unsigned& r1, unsigned& r2, unsigned& r3,
                                       const __half* p)
{
    unsigned s = (unsigned)__cvta_generic_to_shared(p);
    asm volatile("ldmatrix.sync.aligned.m8n8.x4.trans.shared.b16 {%0,%1,%2,%3}, [%4];"
                 : "=r"(r0), "=r"(r1), "=r"(r2), "=r"(r3) : "r"(s));
}

// ---------------- fused preprocessing (one launch) ----------------
__global__ __launch_bounds__(256) void prep_all(
    const float* __restrict__ h,
    const float* __restrict__ Wq, const float* __restrict__ Wk,
    const float* __restrict__ Wv, const float* __restrict__ Wo,
    const float* __restrict__ edge, const int* __restrict__ mask,
    __half* __restrict__ h16, __half* __restrict__ w16, __half* __restrict__ em)
{
    int i = blockIdx.x * 256 + threadIdx.x;
    if (i < N_H4) {
        float4 v = ((const float4*)h)[i];
        __half2* d = (__half2*)h16 + (size_t)i * 2;
        d[0] = __floats2half2_rn(v.x, v.y);
        d[1] = __floats2half2_rn(v.z, v.w);
    } else if (i < N_H4 + 4 * N_W4) {
        int j = i - N_H4;
        int which = j >> 14, off = j & (N_W4 - 1);
        const float* W = which == 0 ? Wq : which == 1 ? Wk : which == 2 ? Wv : Wo;
        float4 v = ((const float4*)W)[off];
        __half2* d = (__half2*)w16 + ((size_t)which * N_W4 + off) * 2;
        d[0] = __floats2half2_rn(v.x, v.y);
        d[1] = __floats2half2_rn(v.z, v.w);
    } else if (i < N_TOT4) {
        const float QNAN = __int_as_float(0x7fc00000);
        int j = i - (N_H4 + 4 * N_W4);
        float4 e = ((const float4*)edge)[j];
        int4   m = ((const int4*)mask)[j];
        __half2* d = (__half2*)em + (size_t)j * 2;
        d[0] = __floats2half2_rn(m.x ? e.x : QNAN, m.y ? e.y : QNAN);
        d[1] = __floats2half2_rn(m.z ? e.z : QNAN, m.w ? e.w : QNAN);
    }
}

// ----------------------------------------------------------------------------
// GEMM core body (shared by qkv/out): 128x128 tile, BK=32, ldmatrix fragments.
// ----------------------------------------------------------------------------
#define GEMM_BODY(X, W, ACC)                                                         \
    const int srow = t >> 2, sc = t & 3;                                             \
    _Pragma("unroll")                                                                \
    for (int i = 0; i < 2; ++i) {                                                    \
        int row = srow + i * 64;                                                     \
        cp16(&Xs[0][row * 40 + sc * 8], X + (size_t)(m0 + row) * 256 + sc * 8);      \
        cp16(&Ws[0][row * 40 + sc * 8], W + (size_t)(n0 + row) * 256 + sc * 8);      \
    }                                                                                \
    CP_COMMIT();                                                                     \
    const int arow = wm + (lane & 7) + ((lane >> 3) & 1) * 8;                        \
    const int acol = ((lane >> 4) << 3);                                             \
    const int brow = wn + ((lane >> 4) << 3) + (lane & 7);                           \
    const int bcol = ((lane >> 3) & 1) << 3;                                         \
    for (int p = 0; p < 8; ++p) {                                                    \
        CP_WAIT0();                                                                  \
        __syncthreads();                                                             \
        if (p < 7) {                                                                 \
            int k0 = (p + 1) * 32, buf = (p + 1) & 1;                                \
            _Pragma("unroll")                                                        \
            for (int i = 0; i < 2; ++i) {                                            \
                int row = srow + i * 64;                                             \
                cp16(&Xs[buf][row * 40 + sc * 8], X + (size_t)(m0 + row) * 256 + k0 + sc * 8); \
                cp16(&Ws[buf][row * 40 + sc * 8], W + (size_t)(n0 + row) * 256 + k0 + sc * 8); \
            }                                                                        \
        }                                                                            \
        CP_COMMIT();                                                                 \
        const __half* Xb = Xs[p & 1];                                                \
        const __half* Wb = Ws[p & 1];                                                \
        _Pragma("unroll")                                                            \
        for (int kc = 0; kc < 2; ++kc) {                                             \
            unsigned a[4][4], bb[4][2];                                              \
            _Pragma("unroll")                                                        \
            for (int mt = 0; mt < 4; ++mt)                                           \
                ldsm4(a[mt][0], a[mt][1], a[mt][2], a[mt][3],                        \
                      Xb + (arow + mt * 16) * 40 + kc * 16 + acol);                  \
            _Pragma("unroll")                                                        \
            for (int np = 0; np < 2; ++np)                                           \
                ldsm4(bb[np * 2][0], bb[np * 2][1], bb[np * 2 + 1][0], bb[np * 2 + 1][1], \
                      Wb + (brow + np * 16) * 40 + kc * 16 + bcol);                  \
            _Pragma("unroll")                                                        \
            for (int mt = 0; mt < 4; ++mt)                                           \
                _Pragma("unroll")                                                    \
                for (int nt = 0; nt < 4; ++nt)                                       \
                    mma_f16(ACC[mt][nt], a[mt][0], a[mt][1], a[mt][2], a[mt][3],     \
                            bb[nt][0], bb[nt][1]);                                   \
        }                                                                            \
    }

// Fused QKV GEMM: grid (6,128); bx>>1 selects Q/K/V; Q pre-scaled.
__global__ __launch_bounds__(256, 2) void gemm_qkv(const __half* __restrict__ X,
                                                   const __half* __restrict__ Wcat,
                                                   __half* __restrict__ Qd,
                                                   __half* __restrict__ Kd,
                                                   __half* __restrict__ Vd)
{
    __shared__ __half Xs[2][128 * 40];
    __shared__ __half Ws[2][128 * 40];

    const int t = threadIdx.x, warp = t >> 5, lane = t & 31;
    const int g = lane >> 2, l = lane & 3;
    const int m0 = blockIdx.y * 128, n0 = blockIdx.x * 128;
    const int wm = (warp >> 2) * 64, wn = (warp & 3) * 32;
    const int which = blockIdx.x >> 1;
    __half* dst = which == 0 ? Qd : which == 1 ? Kd : Vd;
    const int nloc = n0 & 255;
    const float oscale = (which == 0) ? 0.17677669529663687f * 1.4426950408889634f : 1.0f;

    float acc[4][4][4];
#pragma unroll
    for (int mt = 0; mt < 4; ++mt)
#pragma unroll
        for (int nt = 0; nt < 4; ++nt)
#pragma unroll
            for (int i = 0; i < 4; ++i) acc[mt][nt][i] = 0.f;

    GEMM_BODY(X, Wcat, acc)

#pragma unroll
    for (int mt = 0; mt < 4; ++mt) {
#pragma unroll
        for (int nt = 0; nt < 4; ++nt) {
            int r = m0 + wm + mt * 16 + g;
            int c = nloc + wn + nt * 8 + 2 * l;
            *(__half2*)(dst + (size_t)r * 256 + c) =
                __floats2half2_rn(acc[mt][nt][0] * oscale, acc[mt][nt][1] * oscale);
            *(__half2*)(dst + (size_t)(r + 8) * 256 + c) =
                __floats2half2_rn(acc[mt][nt][2] * oscale, acc[mt][nt][3] * oscale);
        }
    }
}

// Output GEMM: fp32 out
__global__ __launch_bounds__(256, 2) void gemm_out(const __half* __restrict__ X,
                                                   const __half* __restrict__ W,
                                                   float* __restrict__ C)
{
    __shared__ __half Xs[2][128 * 40];
    __shared__ __half Ws[2][128 * 40];

    const int t = threadIdx.x, warp = t >> 5, lane = t & 31;
    const int g = lane >> 2, l = lane & 3;
    const int m0 = blockIdx.y * 128, n0 = blockIdx.x * 128;
    const int wm = (warp >> 2) * 64, wn = (warp & 3) * 32;

    float acc[4][4][4];
#pragma unroll
    for (int mt = 0; mt < 4; ++mt)
#pragma unroll
        for (int nt = 0; nt < 4; ++nt)
#pragma unroll
            for (int i = 0; i < 4; ++i) acc[mt][nt][i] = 0.f;

    GEMM_BODY(X, W, acc)

#pragma unroll
    for (int mt = 0; mt < 4; ++mt) {
#pragma unroll
        for (int nt = 0; nt < 4; ++nt) {
            int r = m0 + wm + mt * 16 + g;
            int c = n0 + wn + nt * 8 + 2 * l;
            *(float2*)(C + (size_t)r * 256 + c)       = make_float2(acc[mt][nt][0], acc[mt][nt][1]);
            *(float2*)(C + (size_t)(r + 8) * 256 + c) = make_float2(acc[mt][nt][2], acc[mt][nt][3]);
        }
    }
}

// ----------------------------------------------------------------------------
// Attention (fp16): block = 64 queries x one (b,h), 128 threads (4 warps).
// ldmatrix for Q/K/em fragments; p via ex2.approx.f16x2 -> PV A-fragments.
// ----------------------------------------------------------------------------
#define KLDH 40   // K/V row stride halves (80B) -> conflict-free
#define ELDH 72   // em row stride halves (144B) -> conflict-free

__global__ __launch_bounds__(128, 4) void attn_f16(
    const __half* __restrict__ Qh, const __half* __restrict__ Kh,
    const __half* __restrict__ Vh, const __half* __restrict__ em,
    const float* __restrict__ We, __half* __restrict__ AOh)
{
    __shared__ __half Ks[2][64 * KLDH];
    __shared__ __half Vs[2][64 * KLDH];
    __shared__ __half Es[2][64 * ELDH];

    const int t = threadIdx.x, warp = t >> 5, lane = t & 31;
    const int g = lane >> 2, l = lane & 3;
    const int bh = blockIdx.y;
    const int b  = bh >> 3, hh = bh & 7;
    const int q0 = blockIdx.x * 64;
    const size_t bN = (size_t)b * NSEQ;
    const int R0 = warp * 16 + g;
    const float we = We[hh] * 1.4426950408889634f;   // log2 domain

    // ldmatrix lane-address components
    const int arow = warp * 16 + (lane & 7) + ((lane >> 3) & 1) * 8;  // A/C row
    const int acol = ((lane >> 4) << 3);                              // A col (halves)
    const int krow = (lane & 7);                                      // K row within block
    const int kcol = ((lane >> 3) << 3);                              // K col (halves)

    // ---- stage Q (64x32, pre-scaled) into Ks[0], fragments via ldmatrix
#pragma unroll
    for (int i = 0; i < 2; ++i) {
        int idx = t + i * 128;
        int row = idx >> 2, c = idx & 3;
        uint4 v = *(const uint4*)(Qh + ((bN + q0 + row) * DMODEL) + hh * HDIM + c * 8);
        *(uint4*)&Ks[0][row * KLDH + c * 8] = v;
    }
    __syncthreads();

    unsigned qa[2][4];
    ldsm4(qa[0][0], qa[0][1], qa[0][2], qa[0][3], Ks[0] + arow * KLDH + acol);
    ldsm4(qa[1][0], qa[1][1], qa[1][2], qa[1][3], Ks[0] + arow * KLDH + 16 + acol);
    __syncthreads();

    float m0r = -1e30f, m1r = -1e30f, l0r = 0.f, l1r = 0.f;
    float o[4][4];
#pragma unroll
    for (int nt = 0; nt < 4; ++nt)
#pragma unroll
        for (int i = 0; i < 4; ++i) o[nt][i] = 0.f;

    const int kv_row = t >> 2, kv_c = t & 3;
    const int em_row = t >> 3, em_c = t & 7;

#pragma unroll
    for (int i = 0; i < 2; ++i) {
        int row = kv_row + i * 32;
        cp16(&Ks[0][row * KLDH + kv_c * 8], Kh + (bN + row) * DMODEL + hh * HDIM + kv_c * 8);
        cp16(&Vs[0][row * KLDH + kv_c * 8], Vh + (bN + row) * DMODEL + hh * HDIM + kv_c * 8);
    }
#pragma unroll
    for (int i = 0; i < 4; ++i) {
        int row = em_row + i * 16;
        cp16(&Es[0][row * ELDH + em_c * 8], em + ((bN + q0 + row) * NSEQ) + em_c * 8);
    }
    CP_COMMIT();

    for (int it = 0; it < 8; ++it) {
        CP_WAIT0();
        __syncthreads();
        if (it < 7) {
            int jt = (it + 1) * 64, buf = (it + 1) & 1;
#pragma unroll
            for (int i = 0; i < 2; ++i) {
                int row = kv_row + i * 32;
                cp16(&Ks[buf][row * KLDH + kv_c * 8],
                     Kh + (bN + jt + row) * DMODEL + hh * HDIM + kv_c * 8);
                cp16(&Vs[buf][row * KLDH + kv_c * 8],
                     Vh + (bN + jt + row) * DMODEL + hh * HDIM + kv_c * 8);
            }
#pragma unroll
            for (int i = 0; i < 4; ++i) {
                int row = em_row + i * 16;
                cp16(&Es[buf][row * ELDH + em_c * 8],
                     em + ((bN + q0 + row) * NSEQ) + jt + em_c * 8);
            }
        }
        CP_COMMIT();

        const __half* Kb = Ks[it & 1];
        const __half* Eb = Es[it & 1];
        const __half* Vb = Vs[it & 1];

        // ---- S = Q K^T : K fragments via ldmatrix.x4 (d0..31 in one load)
        float s[8][4];
#pragma unroll
        for (int nt = 0; nt < 8; ++nt) {
            s[nt][0] = s[nt][1] = s[nt][2] = s[nt][3] = 0.f;
            unsigned b0, b1, b2, b3;
            ldsm4(b0, b1, b2, b3, Kb + (8 * nt + krow) * KLDH + kcol);
            mma_f16(s[nt], qa[0][0], qa[0][1], qa[0][2], qa[0][3], b0, b1);
            mma_f16(s[nt], qa[1][0], qa[1][1], qa[1][2], qa[1][3], b2, b3);
        }

        // ---- bias (ldmatrix, C-layout) + mask(NaN) + online max
        float mn0 = m0r, mn1 = m1r;
#pragma unroll
        for (int i = 0; i < 4; ++i) {
            unsigned e0, e1, e2, e3;
            ldsm4(e0, e1, e2, e3, Eb + arow * ELDH + i * 16 + acol);
            float2 f0 = __half22float2(*(__half2*)&e0);
            float2 f1 = __half22float2(*(__half2*)&e1);
            float2 f2 = __half22float2(*(__half2*)&e2);
            float2 f3 = __half22float2(*(__half2*)&e3);
            int n0i = 2 * i, n1i = 2 * i + 1;
            s[n0i][0] = fmaxf(fmaf(we, f0.x, s[n0i][0]), -1e30f);
            s[n0i][1] = fmaxf(fmaf(we, f0.y, s[n0i][1]), -1e30f);
            s[n0i][2] = fmaxf(fmaf(we, f1.x, s[n0i][2]), -1e30f);
            s[n0i][3] = fmaxf(fmaf(we, f1.y, s[n0i][3]), -1e30f);
            s[n1i][0] = fmaxf(fmaf(we, f2.x, s[n1i][0]), -1e30f);
            s[n1i][1] = fmaxf(fmaf(we, f2.y, s[n1i][1]), -1e30f);
            s[n1i][2] = fmaxf(fmaf(we, f3.x, s[n1i][2]), -1e30f);
            s[n1i][3] = fmaxf(fmaf(we, f3.y, s[n1i][3]), -1e30f);
            mn0 = fmaxf(mn0, fmaxf(fmaxf(s[n0i][0], s[n0i][1]), fmaxf(s[n1i][0], s[n1i][1])));
            mn1 = fmaxf(mn1, fmaxf(fmaxf(s[n0i][2], s[n0i][3]), fmaxf(s[n1i][2], s[n1i][3])));
        }
        mn0 = fmaxf(mn0, __shfl_xor_sync(0xffffffff, mn0, 1));
        mn0 = fmaxf(mn0, __shfl_xor_sync(0xffffffff, mn0, 2));
        mn1 = fmaxf(mn1, __shfl_xor_sync(0xffffffff, mn1, 1));
        mn1 = fmaxf(mn1, __shfl_xor_sync(0xffffffff, mn1, 2));

        float corr0 = exp2f(m0r - mn0);
        float corr1 = exp2f(m1r - mn1);
        m0r = mn0; m1r = mn1;

        // ---- p = ex2.f16x2(s - mn): directly PV A-fragments
        unsigned ph[8][2];
        float ps0 = 0.f, ps1 = 0.f;
#pragma unroll
        for (int nt = 0; nt < 8; ++nt) {
            __half2 x01 = __floats2half2_rn(s[nt][0] - mn0, s[nt][1] - mn0);
            __half2 x23 = __floats2half2_rn(s[nt][2] - mn1, s[nt][3] - mn1);
            __half2 p01 = h2exp2(x01);
            __half2 p23 = h2exp2(x23);
            ph[nt][0] = *(unsigned*)&p01;
            ph[nt][1] = *(unsigned*)&p23;
            float2 f01 = __half22float2(p01);
            float2 f23 = __half22float2(p23);
            ps0 += f01.x + f01.y;
            ps1 += f23.x + f23.y;
        }
        ps0 += __shfl_xor_sync(0xffffffff, ps0, 1);
        ps0 += __shfl_xor_sync(0xffffffff, ps0, 2);
        ps1 += __shfl_xor_sync(0xffffffff, ps1, 1);
        ps1 += __shfl_xor_sync(0xffffffff, ps1, 2);
        l0r = l0r * corr0 + ps0;
        l1r = l1r * corr1 + ps1;

#pragma unroll
        for (int nt = 0; nt < 4; ++nt) {
            o[nt][0] *= corr0; o[nt][1] *= corr0;
            o[nt][2] *= corr1; o[nt][3] *= corr1;
        }

        // ---- O += P @ V
        const int vkey = ((lane >> 3) & 1) << 3;
        const int vd   = ((lane >> 4) & 1) << 3;
        const int vr   = lane & 7;
#pragma unroll
        for (int kc = 0; kc < 4; ++kc) {
            unsigned a0 = ph[2 * kc][0];
            unsigned a1 = ph[2 * kc][1];
            unsigned a2 = ph[2 * kc + 1][0];
            unsigned a3 = ph[2 * kc + 1][1];
            unsigned v0, v1, v2, v3, v4, v5, v6, v7;
            const __half* base = Vb + (16 * kc + vkey + vr) * KLDH + vd;
            ldsm4t(v0, v1, v2, v3, base);
            ldsm4t(v4, v5, v6, v7, base + 16);
            mma_f16(o[0], a0, a1, a2, a3, v0, v1);
            mma_f16(o[1], a0, a1, a2, a3, v2, v3);
            mma_f16(o[2], a0, a1, a2, a3, v4, v5);
            mma_f16(o[3], a0, a1, a2, a3, v6, v7);
        }
    }

    // ---- write output (fp16)
    const float inv0 = 1.0f / l0r;
    const float inv1 = 1.0f / l1r;
#pragma unroll
    for (int nt = 0; nt < 4; ++nt) {
        int c = hh * HDIM + nt * 8 + 2 * l;
        *(__half2*)(AOh + (bN + q0 + R0) * DMODEL + c) =
            __floats2half2_rn(o[nt][0] * inv0, o[nt][1] * inv0);
        *(__half2*)(AOh + (bN + q0 + R0 + 8) * DMODEL + c) =
            __floats2half2_rn(o[nt][2] * inv1, o[nt][3] * inv1);
    }
}

// ----------------------------------------------------------------------------
// launch
// ----------------------------------------------------------------------------
extern "C" void kernel_launch(void* const* d_in, const int* in_sizes, int n_in,
                              void* d_out, int out_size)
{
    const float* h    = (const float*)d_in[0];
    const float* edge = (const float*)d_in[1];
    const int*   mask = (const int*)  d_in[2];
    const float* Wq   = (const float*)d_in[3];
    const float* Wk   = (const float*)d_in[4];
    const float* Wv   = (const float*)d_in[5];
    const float* We   = (const float*)d_in[6];
    const float* Wo   = (const float*)d_in[7];
    float* out = (float*)d_out;

    __half *h16, *q16, *k16, *v16, *ao16, *emh, *w16;
    cudaGetSymbolAddress((void**)&h16,  g_h16);
    cudaGetSymbolAddress((void**)&q16,  g_q16);
    cudaGetSymbolAddress((void**)&k16,  g_k16);
    cudaGetSymbolAddress((void**)&v16,  g_v16);
    cudaGetSymbolAddress((void**)&ao16, g_ao16);
    cudaGetSymbolAddress((void**)&emh,  g_em);
    cudaGetSymbolAddress((void**)&w16,  g_w16);

    prep_all<<<N_TOT4 / 256, 256>>>(h, Wq, Wk, Wv, Wo, edge, mask, h16, w16, emh);

    gemm_qkv<<<dim3(6, MROWS / 128), 256>>>(h16, w16, q16, k16, v16);

    attn_f16<<<dim3(NSEQ / 64, BATCH * NHEAD), 128>>>(q16, k16, v16, emh, We, ao16);

    gemm_out<<<dim3(2, MROWS / 128), 256>>>(ao16, w16 + 3 * DMODEL * DMODEL, out);
}

// round 8
// speedup vs baseline: 2.1748x; 1.0023x over previous
#include <cuda_runtime.h>
#include <cuda_fp16.h>
#include <math.h>

// ----------------------------------------------------------------------------
// EdgeBiasedAttention — fp16 mma.m16n8k16 pipeline (v8)
// v8: 4-stage cp.async pipeline in GEMMs (latency was unhidden at 2 stages);
//     prep kernel widened to 8 floats/thread.
// B=32, N=512, D=256, H=8, HD=32
// ----------------------------------------------------------------------------

#define BATCH 32
#define NSEQ  512
#define DMODEL 256
#define NHEAD 8
#define HDIM  32
#define MROWS (BATCH * NSEQ)  // 16384

#define N_H8 (MROWS * DMODEL / 8)          // 524288
#define N_W8 (DMODEL * DMODEL / 8)         // 8192
#define N_E8 (BATCH * NSEQ * NSEQ / 8)     // 1048576
#define N_TOT8 (N_H8 + 4 * N_W8 + N_E8)    // 1605632

// fp16 scratch
__device__ __half g_h16 [MROWS * DMODEL];
__device__ __half g_q16 [MROWS * DMODEL];
__device__ __half g_k16 [MROWS * DMODEL];
__device__ __half g_v16 [MROWS * DMODEL];
__device__ __half g_ao16[MROWS * DMODEL];
__device__ __half g_em  [BATCH * NSEQ * NSEQ];   // masked edge (NaN = masked)
__device__ __half g_w16 [4 * DMODEL * DMODEL];   // Wq, Wk, Wv, Wo fp16

// ---------------- helpers ----------------
__device__ __forceinline__ void mma_f16(float c[4],
                                        unsigned a0, unsigned a1, unsigned a2, unsigned a3,
                                        unsigned b0, unsigned b1)
{
    asm volatile(
        "mma.sync.aligned.m16n8k16.row.col.f32.f16.f16.f32 "
        "{%0,%1,%2,%3}, {%4,%5,%6,%7}, {%8,%9}, {%0,%1,%2,%3};"
        : "+f"(c[0]), "+f"(c[1]), "+f"(c[2]), "+f"(c[3])
        : "r"(a0), "r"(a1), "r"(a2), "r"(a3), "r"(b0), "r"(b1));
}

__device__ __forceinline__ void cp16(void* sdst, const void* gsrc) {
    unsigned s = (unsigned)__cvta_generic_to_shared(sdst);
    asm volatile("cp.async.cg.shared.global [%0], [%1], 16;" :: "r"(s), "l"(gsrc));
}
#define CP_COMMIT() asm volatile("cp.async.commit_group;")
#define CP_WAIT0()  asm volatile("cp.async.wait_group 0;" ::: "memory")
#define CP_WAIT2()  asm volatile("cp.async.wait_group 2;" ::: "memory")

__device__ __forceinline__ void ldsm4(unsigned& r0, unsigned& r1, unsigned& r2, unsigned& r3,
                                      const __half* p)
{
    unsigned s = (unsigned)__cvta_generic_to_shared(p);
    asm volatile("ldmatrix.sync.aligned.m8n8.x4.shared.b16 {%0,%1,%2,%3}, [%4];"
                 : "=r"(r0), "=r"(r1), "=r"(r2), "=r"(r3) : "r"(s));
}
__device__ __forceinline__ void ldsm4t(unsigned& r0, unsigned& r1, unsigned& r2, unsigned& r3,
                                       const __half* p)
{
    unsigned s = (unsigned)__cvta_generic_to_shared(p);
    asm volatile("ldmatrix.sync.aligned.m8n8.x4.trans.shared.b16 {%0,%1,%2,%3}, [%4];"
                 : "=r"(r0), "=r"(r1), "=r"(r2), "=r"(r3) : "r"(s));
}

__device__ __forceinline__ uint4 pack8(float4 a, float4 b) {
    uint4 o;
    __half2 h0 = __floats2half2_rn(a.x, a.y);
    __half2 h1 = __floats2half2_rn(a.z, a.w);
    __half2 h2 = __floats2half2_rn(b.x, b.y);
    __half2 h3 = __floats2half2_rn(b.z, b.w);
    o.x = *(unsigned*)&h0; o.y = *(unsigned*)&h1;
    o.z = *(unsigned*)&h2; o.w = *(unsigned*)&h3;
    return o;
}

// ---------------- fused preprocessing (one launch, 8 floats/thread) ----------
__global__ __launch_bounds__(256) void prep_all(
    const float* __restrict__ h,
    const float* __restrict__ Wq, const float* __restrict__ Wk,
    const float* __restrict__ Wv, const float* __restrict__ Wo,
    const float* __restrict__ edge, const int* __restrict__ mask,
    __half* __restrict__ h16, __half* __restrict__ w16, __half* __restrict__ em)
{
    int i = blockIdx.x * 256 + threadIdx.x;
    if (i < N_H8) {
        const float4* s = (const float4*)h + (size_t)i * 2;
        ((uint4*)h16)[i] = pack8(s[0], s[1]);
    } else if (i < N_H8 + 4 * N_W8) {
        int j = i - N_H8;
        int which = j >> 13, off = j & (N_W8 - 1);
        const float* W = which == 0 ? Wq : which == 1 ? Wk : which == 2 ? Wv : Wo;
        const float4* s = (const float4*)W + (size_t)off * 2;
        ((uint4*)w16)[(size_t)which * N_W8 + off] = pack8(s[0], s[1]);
    } else if (i < N_TOT8) {
        const float QNAN = __int_as_float(0x7fc00000);
        int j = i - (N_H8 + 4 * N_W8);
        const float4* es = (const float4*)edge + (size_t)j * 2;
        const int4*   ms = (const int4*)mask + (size_t)j * 2;
        float4 e0 = es[0], e1 = es[1];
        int4   m0 = ms[0], m1 = ms[1];
        float4 f0 = make_float4(m0.x ? e0.x : QNAN, m0.y ? e0.y : QNAN,
                                m0.z ? e0.z : QNAN, m0.w ? e0.w : QNAN);
        float4 f1 = make_float4(m1.x ? e1.x : QNAN, m1.y ? e1.y : QNAN,
                                m1.z ? e1.z : QNAN, m1.w ? e1.w : QNAN);
        ((uint4*)em)[j] = pack8(f0, f1);
    }
}

// ----------------------------------------------------------------------------
// GEMM core: 128x128 tile, BK=32, 4-stage cp.async pipeline, ldmatrix frags.
// Dynamic smem: Xs[4][128*40], Ws[4][128*40]  (81920 B)
// ----------------------------------------------------------------------------
#define GSTG (128 * 40)
#define GEMM_SMEM_BYTES (8 * GSTG * 2)

#define GEMM_BODY(X, W, ACC)                                                         \
    __half* Xs = gsm;                                                                \
    __half* Ws = gsm + 4 * GSTG;                                                     \
    const int srow = t >> 2, sc = t & 3;                                             \
    _Pragma("unroll")                                                                \
    for (int st = 0; st < 3; ++st) {                                                 \
        int k0 = st * 32;                                                            \
        _Pragma("unroll")                                                            \
        for (int i = 0; i < 2; ++i) {                                                \
            int row = srow + i * 64;                                                 \
            cp16(Xs + st * GSTG + row * 40 + sc * 8, X + (size_t)(m0 + row) * 256 + k0 + sc * 8); \
            cp16(Ws + st * GSTG + row * 40 + sc * 8, W + (size_t)(n0 + row) * 256 + k0 + sc * 8); \
        }                                                                            \
        CP_COMMIT();                                                                 \
    }                                                                                \
    const int arow = wm + (lane & 7) + ((lane >> 3) & 1) * 8;                        \
    const int acol = ((lane >> 4) << 3);                                             \
    const int brow = wn + ((lane >> 4) << 3) + (lane & 7);                           \
    const int bcol = ((lane >> 3) & 1) << 3;                                         \
    for (int p = 0; p < 8; ++p) {                                                    \
        CP_WAIT2();                                                                  \
        __syncthreads();                                                             \
        if (p < 5) {                                                                 \
            int k0 = (p + 3) * 32, buf = (p + 3) & 3;                                \
            _Pragma("unroll")                                                        \
            for (int i = 0; i < 2; ++i) {                                            \
                int row = srow + i * 64;                                             \
                cp16(Xs + buf * GSTG + row * 40 + sc * 8, X + (size_t)(m0 + row) * 256 + k0 + sc * 8); \
                cp16(Ws + buf * GSTG + row * 40 + sc * 8, W + (size_t)(n0 + row) * 256 + k0 + sc * 8); \
            }                                                                        \
        }                                                                            \
        CP_COMMIT();                                                                 \
        const __half* Xb = Xs + (p & 3) * GSTG;                                      \
        const __half* Wb = Ws + (p & 3) * GSTG;                                      \
        _Pragma("unroll")                                                            \
        for (int kc = 0; kc < 2; ++kc) {                                             \
            unsigned a[4][4], bb[4][2];                                              \
            _Pragma("unroll")                                                        \
            for (int mt = 0; mt < 4; ++mt)                                           \
                ldsm4(a[mt][0], a[mt][1], a[mt][2], a[mt][3],                        \
                      Xb + (arow + mt * 16) * 40 + kc * 16 + acol);                  \
            _Pragma("unroll")                                                        \
            for (int np = 0; np < 2; ++np)                                           \
                ldsm4(bb[np * 2][0], bb[np * 2][1], bb[np * 2 + 1][0], bb[np * 2 + 1][1], \
                      Wb + (brow + np * 16) * 40 + kc * 16 + bcol);                  \
            _Pragma("unroll")                                                        \
            for (int mt = 0; mt < 4; ++mt)                                           \
                _Pragma("unroll")                                                    \
                for (int nt = 0; nt < 4; ++nt)                                       \
                    mma_f16(ACC[mt][nt], a[mt][0], a[mt][1], a[mt][2], a[mt][3],     \
                            bb[nt][0], bb[nt][1]);                                   \
        }                                                                            \
    }

// Fused QKV GEMM: grid (6,128); bx>>1 selects Q/K/V; Q pre-scaled.
__global__ __launch_bounds__(256, 2) void gemm_qkv(const __half* __restrict__ X,
                                                   const __half* __restrict__ Wcat,
                                                   __half* __restrict__ Qd,
                                                   __half* __restrict__ Kd,
                                                   __half* __restrict__ Vd)
{
    extern __shared__ __half gsm[];

    const int t = threadIdx.x, warp = t >> 5, lane = t & 31;
    const int g = lane >> 2, l = lane & 3;
    const int m0 = blockIdx.y * 128, n0 = blockIdx.x * 128;
    const int wm = (warp >> 2) * 64, wn = (warp & 3) * 32;
    const int which = blockIdx.x >> 1;
    __half* dst = which == 0 ? Qd : which == 1 ? Kd : Vd;
    const int nloc = n0 & 255;
    const float oscale = (which == 0) ? 0.17677669529663687f * 1.4426950408889634f : 1.0f;

    float acc[4][4][4];
#pragma unroll
    for (int mt = 0; mt < 4; ++mt)
#pragma unroll
        for (int nt = 0; nt < 4; ++nt)
#pragma unroll
            for (int i = 0; i < 4; ++i) acc[mt][nt][i] = 0.f;

    GEMM_BODY(X, Wcat, acc)

#pragma unroll
    for (int mt = 0; mt < 4; ++mt) {
#pragma unroll
        for (int nt = 0; nt < 4; ++nt) {
            int r = m0 + wm + mt * 16 + g;
            int c = nloc + wn + nt * 8 + 2 * l;
            *(__half2*)(dst + (size_t)r * 256 + c) =
                __floats2half2_rn(acc[mt][nt][0] * oscale, acc[mt][nt][1] * oscale);
            *(__half2*)(dst + (size_t)(r + 8) * 256 + c) =
                __floats2half2_rn(acc[mt][nt][2] * oscale, acc[mt][nt][3] * oscale);
        }
    }
}

// Output GEMM: fp32 out
__global__ __launch_bounds__(256, 2) void gemm_out(const __half* __restrict__ X,
                                                   const __half* __restrict__ W,
                                                   float* __restrict__ C)
{
    extern __shared__ __half gsm[];

    const int t = threadIdx.x, warp = t >> 5, lane = t & 31;
    const int g = lane >> 2, l = lane & 3;
    const int m0 = blockIdx.y * 128, n0 = blockIdx.x * 128;
    const int wm = (warp >> 2) * 64, wn = (warp & 3) * 32;

    float acc[4][4][4];
#pragma unroll
    for (int mt = 0; mt < 4; ++mt)
#pragma unroll
        for (int nt = 0; nt < 4; ++nt)
#pragma unroll
            for (int i = 0; i < 4; ++i) acc[mt][nt][i] = 0.f;

    GEMM_BODY(X, W, acc)

#pragma unroll
    for (int mt = 0; mt < 4; ++mt) {
#pragma unroll
        for (int nt = 0; nt < 4; ++nt) {
            int r = m0 + wm + mt * 16 + g;
            int c = n0 + wn + nt * 8 + 2 * l;
            *(float2*)(C + (size_t)r * 256 + c)       = make_float2(acc[mt][nt][0], acc[mt][nt][1]);
            *(float2*)(C + (size_t)(r + 8) * 256 + c) = make_float2(acc[mt][nt][2], acc[mt][nt][3]);
        }
    }
}

// ----------------------------------------------------------------------------
// Attention (fp16) — unchanged from v7 (latency already hidden there).
// ----------------------------------------------------------------------------
#define KLDH 40   // K/V row stride halves (80B) -> conflict-free
#define ELDH 72   // em row stride halves (144B) -> conflict-free

__global__ __launch_bounds__(128, 4) void attn_f16(
    const __half* __restrict__ Qh, const __half* __restrict__ Kh,
    const __half* __restrict__ Vh, const __half* __restrict__ em,
    const float* __restrict__ We, __half* __restrict__ AOh)
{
    __shared__ __half Ks[2][64 * KLDH];
    __shared__ __half Vs[2][64 * KLDH];
    __shared__ __half Es[2][64 * ELDH];

    const int t = threadIdx.x, warp = t >> 5, lane = t & 31;
    const int g = lane >> 2, l = lane & 3;
    const int bh = blockIdx.y;
    const int b  = bh >> 3, hh = bh & 7;
    const int q0 = blockIdx.x * 64;
    const size_t bN = (size_t)b * NSEQ;
    const int R0 = warp * 16 + g;
    const float we = We[hh] * 1.4426950408889634f;   // log2 domain

    const int arow = warp * 16 + (lane & 7) + ((lane >> 3) & 1) * 8;
    const int acol = ((lane >> 4) << 3);
    const int krow = (lane & 7);
    const int kcol = ((lane >> 3) << 3);

#pragma unroll
    for (int i = 0; i < 2; ++i) {
        int idx = t + i * 128;
        int row = idx >> 2, c = idx & 3;
        uint4 v = *(const uint4*)(Qh + ((bN + q0 + row) * DMODEL) + hh * HDIM + c * 8);
        *(uint4*)&Ks[0][row * KLDH + c * 8] = v;
    }
    __syncthreads();

    unsigned qa[2][4];
    ldsm4(qa[0][0], qa[0][1], qa[0][2], qa[0][3], Ks[0] + arow * KLDH + acol);
    ldsm4(qa[1][0], qa[1][1], qa[1][2], qa[1][3], Ks[0] + arow * KLDH + 16 + acol);
    __syncthreads();

    float m0r = -1e30f, m1r = -1e30f, l0r = 0.f, l1r = 0.f;
    float o[4][4];
#pragma unroll
    for (int nt = 0; nt < 4; ++nt)
#pragma unroll
        for (int i = 0; i < 4; ++i) o[nt][i] = 0.f;

    const int kv_row = t >> 2, kv_c = t & 3;
    const int em_row = t >> 3, em_c = t & 7;

#pragma unroll
    for (int i = 0; i < 2; ++i) {
        int row = kv_row + i * 32;
        cp16(&Ks[0][row * KLDH + kv_c * 8], Kh + (bN + row) * DMODEL + hh * HDIM + kv_c * 8);
        cp16(&Vs[0][row * KLDH + kv_c * 8], Vh + (bN + row) * DMODEL + hh * HDIM + kv_c * 8);
    }
#pragma unroll
    for (int i = 0; i < 4; ++i) {
        int row = em_row + i * 16;
        cp16(&Es[0][row * ELDH + em_c * 8], em + ((bN + q0 + row) * NSEQ) + em_c * 8);
    }
    CP_COMMIT();

    for (int it = 0; it < 8; ++it) {
        CP_WAIT0();
        __syncthreads();
        if (it < 7) {
            int jt = (it + 1) * 64, buf = (it + 1) & 1;
#pragma unroll
            for (int i = 0; i < 2; ++i) {
                int row = kv_row + i * 32;
                cp16(&Ks[buf][row * KLDH + kv_c * 8],
                     Kh + (bN + jt + row) * DMODEL + hh * HDIM + kv_c * 8);
                cp16(&Vs[buf][row * KLDH + kv_c * 8],
                     Vh + (bN + jt + row) * DMODEL + hh * HDIM + kv_c * 8);
            }
#pragma unroll
            for (int i = 0; i < 4; ++i) {
                int row = em_row + i * 16;
                cp16(&Es[buf][row * ELDH + em_c * 8],
                     em + ((bN + q0 + row) * NSEQ) + jt + em_c * 8);
            }
        }
        CP_COMMIT();

        const __half* Kb = Ks[it & 1];
        const __half* Eb = Es[it & 1];
        const __half* Vb = Vs[it & 1];

        float s[8][4];
#pragma unroll
        for (int nt = 0; nt < 8; ++nt) {
            s[nt][0] = s[nt][1] = s[nt][2] = s[nt][3] = 0.f;
            unsigned b0, b1, b2, b3;
            ldsm4(b0, b1, b2, b3, Kb + (8 * nt + krow) * KLDH + kcol);
            mma_f16(s[nt], qa[0][0], qa[0][1], qa[0][2], qa[0][3], b0, b1);
            mma_f16(s[nt], qa[1][0], qa[1][1], qa[1][2], qa[1][3], b2, b3);
        }

        float mn0 = m0r, mn1 = m1r;
#pragma unroll
        for (int i = 0; i < 4; ++i) {
            unsigned e0, e1, e2, e3;
            ldsm4(e0, e1, e2, e3, Eb + arow * ELDH + i * 16 + acol);
            float2 f0 = __half22float2(*(__half2*)&e0);
            float2 f1 = __half22float2(*(__half2*)&e1);
            float2 f2 = __half22float2(*(__half2*)&e2);
            float2 f3 = __half22float2(*(__half2*)&e3);
            int n0i = 2 * i, n1i = 2 * i + 1;
            s[n0i][0] = fmaxf(fmaf(we, f0.x, s[n0i][0]), -1e30f);
            s[n0i][1] = fmaxf(fmaf(we, f0.y, s[n0i][1]), -1e30f);
            s[n0i][2] = fmaxf(fmaf(we, f1.x, s[n0i][2]), -1e30f);
            s[n0i][3] = fmaxf(fmaf(we, f1.y, s[n0i][3]), -1e30f);
            s[n1i][0] = fmaxf(fmaf(we, f2.x, s[n1i][0]), -1e30f);
            s[n1i][1] = fmaxf(fmaf(we, f2.y, s[n1i][1]), -1e30f);
            s[n1i][2] = fmaxf(fmaf(we, f3.x, s[n1i][2]), -1e30f);
            s[n1i][3] = fmaxf(fmaf(we, f3.y, s[n1i][3]), -1e30f);
            mn0 = fmaxf(mn0, fmaxf(fmaxf(s[n0i][0], s[n0i][1]), fmaxf(s[n1i][0], s[n1i][1])));
            mn1 = fmaxf(mn1, fmaxf(fmaxf(s[n0i][2], s[n0i][3]), fmaxf(s[n1i][2], s[n1i][3])));
        }
        mn0 = fmaxf(mn0, __shfl_xor_sync(0xffffffff, mn0, 1));
        mn0 = fmaxf(mn0, __shfl_xor_sync(0xffffffff, mn0, 2));
        mn1 = fmaxf(mn1, __shfl_xor_sync(0xffffffff, mn1, 1));
        mn1 = fmaxf(mn1, __shfl_xor_sync(0xffffffff, mn1, 2));

        float corr0 = exp2f(m0r - mn0);
        float corr1 = exp2f(m1r - mn1);
        m0r = mn0; m1r = mn1;

        unsigned ph[8][2];
        float ps0 = 0.f, ps1 = 0.f;
#pragma unroll
        for (int nt = 0; nt < 8; ++nt) {
            __half2 x01 = __floats2half2_rn(s[nt][0] - mn0, s[nt][1] - mn0);
            __half2 x23 = __floats2half2_rn(s[nt][2] - mn1, s[nt][3] - mn1);
            __half2 p01 = h2exp2(x01);
            __half2 p23 = h2exp2(x23);
            ph[nt][0] = *(unsigned*)&p01;
            ph[nt][1] = *(unsigned*)&p23;
            float2 f01 = __half22float2(p01);
            float2 f23 = __half22float2(p23);
            ps0 += f01.x + f01.y;
            ps1 += f23.x + f23.y;
        }
        ps0 += __shfl_xor_sync(0xffffffff, ps0, 1);
        ps0 += __shfl_xor_sync(0xffffffff, ps0, 2);
        ps1 += __shfl_xor_sync(0xffffffff, ps1, 1);
        ps1 += __shfl_xor_sync(0xffffffff, ps1, 2);
        l0r = l0r * corr0 + ps0;
        l1r = l1r * corr1 + ps1;

#pragma unroll
        for (int nt = 0; nt < 4; ++nt) {
            o[nt][0] *= corr0; o[nt][1] *= corr0;
            o[nt][2] *= corr1; o[nt][3] *= corr1;
        }

        const int vkey = ((lane >> 3) & 1) << 3;
        const int vd   = ((lane >> 4) & 1) << 3;
        const int vr   = lane & 7;
#pragma unroll
        for (int kc = 0; kc < 4; ++kc) {
            unsigned a0 = ph[2 * kc][0];
            unsigned a1 = ph[2 * kc][1];
            unsigned a2 = ph[2 * kc + 1][0];
            unsigned a3 = ph[2 * kc + 1][1];
            unsigned v0, v1, v2, v3, v4, v5, v6, v7;
            const __half* base = Vb + (16 * kc + vkey + vr) * KLDH + vd;
            ldsm4t(v0, v1, v2, v3, base);
            ldsm4t(v4, v5, v6, v7, base + 16);
            mma_f16(o[0], a0, a1, a2, a3, v0, v1);
            mma_f16(o[1], a0, a1, a2, a3, v2, v3);
            mma_f16(o[2], a0, a1, a2, a3, v4, v5);
            mma_f16(o[3], a0, a1, a2, a3, v6, v7);
        }
    }

    const float inv0 = 1.0f / l0r;
    const float inv1 = 1.0f / l1r;
#pragma unroll
    for (int nt = 0; nt < 4; ++nt) {
        int c = hh * HDIM + nt * 8 + 2 * l;
        *(__half2*)(AOh + (bN + q0 + R0) * DMODEL + c) =
            __floats2half2_rn(o[nt][0] * inv0, o[nt][1] * inv0);
        *(__half2*)(AOh + (bN + q0 + R0 + 8) * DMODEL + c) =
            __floats2half2_rn(o[nt][2] * inv1, o[nt][3] * inv1);
    }
}

// ----------------------------------------------------------------------------
// launch
// ----------------------------------------------------------------------------
extern "C" void kernel_launch(void* const* d_in, const int* in_sizes, int n_in,
                              void* d_out, int out_size)
{
    const float* h    = (const float*)d_in[0];
    const float* edge = (const float*)d_in[1];
    const int*   mask = (const int*)  d_in[2];
    const float* Wq   = (const float*)d_in[3];
    const float* Wk   = (const float*)d_in[4];
    const float* Wv   = (const float*)d_in[5];
    const float* We   = (const float*)d_in[6];
    const float* Wo   = (const float*)d_in[7];
    float* out = (float*)d_out;

    __half *h16, *q16, *k16, *v16, *ao16, *emh, *w16;
    cudaGetSymbolAddress((void**)&h16,  g_h16);
    cudaGetSymbolAddress((void**)&q16,  g_q16);
    cudaGetSymbolAddress((void**)&k16,  g_k16);
    cudaGetSymbolAddress((void**)&v16,  g_v16);
    cudaGetSymbolAddress((void**)&ao16, g_ao16);
    cudaGetSymbolAddress((void**)&emh,  g_em);
    cudaGetSymbolAddress((void**)&w16,  g_w16);

    cudaFuncSetAttribute(gemm_qkv, cudaFuncAttributeMaxDynamicSharedMemorySize, GEMM_SMEM_BYTES);
    cudaFuncSetAttribute(gemm_out, cudaFuncAttributeMaxDynamicSharedMemorySize, GEMM_SMEM_BYTES);

    prep_all<<<N_TOT8 / 256, 256>>>(h, Wq, Wk, Wv, Wo, edge, mask, h16, w16, emh);

    gemm_qkv<<<dim3(6, MROWS / 128), 256, GEMM_SMEM_BYTES>>>(h16, w16, q16, k16, v16);

    attn_f16<<<dim3(NSEQ / 64, BATCH * NHEAD), 128>>>(q16, k16, v16, emh, We, ao16);

    gemm_out<<<dim3(2, MROWS / 128), 256, GEMM_SMEM_BYTES>>>(ao16, w16 + 3 * DMODEL * DMODEL, out);
}

// round 10
// speedup vs baseline: 2.2167x; 1.0193x over previous
#include <cuda_runtime.h>
#include <cuda_fp16.h>
#include <math.h>

// ----------------------------------------------------------------------------
// EdgeBiasedAttention — v10 (mma.sync path; tcgen05 rejected by sm_100 target)
// GEMMs retiled to 128x64 (3 blocks/SM, latency-hiding via block overlap);
// em-preprocessing fused into gemm_qkv launch as extra streaming blocks;
// attention occupancy 4->5 blocks/SM.
// B=32, N=512, D=256, H=8, HD=32
// ----------------------------------------------------------------------------

#define BATCH 32
#define NSEQ  512
#define DMODEL 256
#define NHEAD 8
#define HDIM  32
#define MROWS (BATCH * NSEQ)  // 16384

#define N_H8 (MROWS * DMODEL / 8)          // 524288
#define N_W8 (DMODEL * DMODEL / 8)         // 8192
#define N_E8 (BATCH * NSEQ * NSEQ / 8)     // 1048576
#define N_HW8 (N_H8 + 4 * N_W8)            // 557056

// fp16 scratch
__device__ __half g_h16 [MROWS * DMODEL];
__device__ __half g_q16 [MROWS * DMODEL];
__device__ __half g_k16 [MROWS * DMODEL];
__device__ __half g_v16 [MROWS * DMODEL];
__device__ __half g_ao16[MROWS * DMODEL];
__device__ __half g_em  [BATCH * NSEQ * NSEQ];   // masked edge (NaN = masked)
__device__ __half g_w16 [4 * DMODEL * DMODEL];   // Wq, Wk, Wv, Wo fp16

// ---------------- helpers ----------------
__device__ __forceinline__ void mma_f16(float c[4],
                                        unsigned a0, unsigned a1, unsigned a2, unsigned a3,
                                        unsigned b0, unsigned b1)
{
    asm volatile(
        "mma.sync.aligned.m16n8k16.row.col.f32.f16.f16.f32 "
        "{%0,%1,%2,%3}, {%4,%5,%6,%7}, {%8,%9}, {%0,%1,%2,%3};"
        : "+f"(c[0]), "+f"(c[1]), "+f"(c[2]), "+f"(c[3])
        : "r"(a0), "r"(a1), "r"(a2), "r"(a3), "r"(b0), "r"(b1));
}

__device__ __forceinline__ void cp16(void* sdst, const void* gsrc) {
    unsigned s = (unsigned)__cvta_generic_to_shared(sdst);
    asm volatile("cp.async.cg.shared.global [%0], [%1], 16;" :: "r"(s), "l"(gsrc));
}
#define CP_COMMIT() asm volatile("cp.async.commit_group;")
#define CP_WAIT0()  asm volatile("cp.async.wait_group 0;" ::: "memory")

__device__ __forceinline__ void ldsm4(unsigned& r0, unsigned& r1, unsigned& r2, unsigned& r3,
                                      const __half* p)
{
    unsigned s = (unsigned)__cvta_generic_to_shared(p);
    asm volatile("ldmatrix.sync.aligned.m8n8.x4.shared.b16 {%0,%1,%2,%3}, [%4];"
                 : "=r"(r0), "=r"(r1), "=r"(r2), "=r"(r3) : "r"(s));
}
__device__ __forceinline__ void ldsm4t(unsigned& r0, unsigned& r1, unsigned& r2, unsigned& r3,
                                       const __half* p)
{
    unsigned s = (unsigned)__cvta_generic_to_shared(p);
    asm volatile("ldmatrix.sync.aligned.m8n8.x4.trans.shared.b16 {%0,%1,%2,%3}, [%4];"
                 : "=r"(r0), "=r"(r1), "=r"(r2), "=r"(r3) : "r"(s));
}

__device__ __forceinline__ uint4 pack8(float4 a, float4 b) {
    uint4 o;
    __half2 h0 = __floats2half2_rn(a.x, a.y);
    __half2 h1 = __floats2half2_rn(a.z, a.w);
    __half2 h2 = __floats2half2_rn(b.x, b.y);
    __half2 h3 = __floats2half2_rn(b.z, b.w);
    o.x = *(unsigned*)&h0; o.y = *(unsigned*)&h1;
    o.z = *(unsigned*)&h2; o.w = *(unsigned*)&h3;
    return o;
}

// ---------------- preprocessing: h + weights only (em fused into gemm_qkv) --
__global__ __launch_bounds__(256) void prep_hw(
    const float* __restrict__ h,
    const float* __restrict__ Wq, const float* __restrict__ Wk,
    const float* __restrict__ Wv, const float* __restrict__ Wo,
    __half* __restrict__ h16, __half* __restrict__ w16)
{
    int i = blockIdx.x * 256 + threadIdx.x;
    if (i < N_H8) {
        const float4* s = (const float4*)h + (size_t)i * 2;
        ((uint4*)h16)[i] = pack8(s[0], s[1]);
    } else if (i < N_HW8) {
        int j = i - N_H8;
        int which = j >> 13, off = j & (N_W8 - 1);
        const float* W = which == 0 ? Wq : which == 1 ? Wk : which == 2 ? Wv : Wo;
        const float4* s = (const float4*)W + (size_t)off * 2;
        ((uint4*)w16)[(size_t)which * N_W8 + off] = pack8(s[0], s[1]);
    }
}

// ----------------------------------------------------------------------------
// GEMM core: 128x64 tile, BK=32, 2-stage cp.async, 8 warps (warp tile 32x32).
// smem static: Xs[2][128*40] + Ws[2][64*40] = 30720 B.
// ----------------------------------------------------------------------------
#define GEMM_BODY(X, W, N0W, ACC)                                                    \
    /* prologue: stage 0 */                                                          \
    {                                                                                \
        int idx = t, row = idx >> 2, c = idx & 3;                                    \
        cp16(&Ws[0][row * 40 + c * 8], W + (size_t)(N0W + row) * 256 + c * 8);       \
        int idx2 = t + 256; int row2 = idx2 >> 2, c2 = idx2 & 3; (void)row2;(void)c2;\
    }                                                                                \
    _Pragma("unroll")                                                                \
    for (int i = 0; i < 2; ++i) {                                                    \
        int idx = t + i * 256, row = idx >> 2, c = idx & 3;                          \
        cp16(&Xs[0][row * 40 + c * 8], X + (size_t)(m0 + row) * 256 + c * 8);        \
    }                                                                                \
    CP_COMMIT();                                                                     \
    const int arow = wm + (lane & 7) + ((lane >> 3) & 1) * 8;                        \
    const int acol = ((lane >> 4) << 3);                                             \
    const int brow = wn + ((lane >> 4) << 3) + (lane & 7);                           \
    const int bcol = ((lane >> 3) & 1) << 3;                                         \
    for (int p = 0; p < 8; ++p) {                                                    \
        CP_WAIT0();                                                                  \
        __syncthreads();                                                             \
        if (p < 7) {                                                                 \
            int k0 = (p + 1) * 32, buf = (p + 1) & 1;                                \
            {                                                                        \
                int row = t >> 2, c = t & 3;                                         \
                cp16(&Ws[buf][row * 40 + c * 8], W + (size_t)(N0W + row) * 256 + k0 + c * 8); \
            }                                                                        \
            _Pragma("unroll")                                                        \
            for (int i = 0; i < 2; ++i) {                                            \
                int idx = t + i * 256, row = idx >> 2, c = idx & 3;                  \
                cp16(&Xs[buf][row * 40 + c * 8], X + (size_t)(m0 + row) * 256 + k0 + c * 8); \
            }                                                                        \
        }                                                                            \
        CP_COMMIT();                                                                 \
        const __half* Xb = Xs[p & 1];                                                \
        const __half* Wb = Ws[p & 1];                                                \
        _Pragma("unroll")                                                            \
        for (int kc = 0; kc < 2; ++kc) {                                             \
            unsigned a[2][4], bb[4][2];                                              \
            _Pragma("unroll")                                                        \
            for (int mt = 0; mt < 2; ++mt)                                           \
                ldsm4(a[mt][0], a[mt][1], a[mt][2], a[mt][3],                        \
                      Xb + (arow + mt * 16) * 40 + kc * 16 + acol);                  \
            _Pragma("unroll")                                                        \
            for (int np = 0; np < 2; ++np)                                           \
                ldsm4(bb[np * 2][0], bb[np * 2][1], bb[np * 2 + 1][0], bb[np * 2 + 1][1], \
                      Wb + (brow + np * 16) * 40 + kc * 16 + bcol);                  \
            _Pragma("unroll")                                                        \
            for (int mt = 0; mt < 2; ++mt)                                           \
                _Pragma("unroll")                                                    \
                for (int nt = 0; nt < 4; ++nt)                                       \
                    mma_f16(ACC[mt][nt], a[mt][0], a[mt][1], a[mt][2], a[mt][3],     \
                            bb[nt][0], bb[nt][1]);                                   \
        }                                                                            \
    }

// Fused QKV GEMM + em preprocessing.
// grid (12, 160): by<128 -> gemm rows; by>=128 -> em-prep streaming blocks.
// bx>>2 selects Q/K/V; (bx&3)*64 is n-offset. Q output pre-scaled.
__global__ __launch_bounds__(256, 3) void gemm_qkv(
    const __half* __restrict__ X, const __half* __restrict__ Wcat,
    __half* __restrict__ Qd, __half* __restrict__ Kd, __half* __restrict__ Vd,
    const float* __restrict__ edge, const int* __restrict__ mask,
    __half* __restrict__ em)
{
    __shared__ __half Xs[2][128 * 40];
    __shared__ __half Ws[2][64 * 40];

    const int t = threadIdx.x;

    if (blockIdx.y >= 128) {
        // ---- em preprocessing block (pure streaming) ----
        const float QNAN = __int_as_float(0x7fc00000);
        int chunk = (blockIdx.y - 128) * 12 + blockIdx.x;   // 0..383
        for (int j = chunk * 256 + t; j < N_E8; j += 384 * 256) {
            const float4* es = (const float4*)edge + (size_t)j * 2;
            const int4*   ms = (const int4*)mask + (size_t)j * 2;
            float4 e0 = es[0], e1 = es[1];
            int4   m0v = ms[0], m1v = ms[1];
            float4 f0 = make_float4(m0v.x ? e0.x : QNAN, m0v.y ? e0.y : QNAN,
                                    m0v.z ? e0.z : QNAN, m0v.w ? e0.w : QNAN);
            float4 f1 = make_float4(m1v.x ? e1.x : QNAN, m1v.y ? e1.y : QNAN,
                                    m1v.z ? e1.z : QNAN, m1v.w ? e1.w : QNAN);
            ((uint4*)em)[j] = pack8(f0, f1);
        }
        return;
    }

    const int warp = t >> 5, lane = t & 31;
    const int g = lane >> 2, l = lane & 3;
    const int m0 = blockIdx.y * 128;
    const int n0w = blockIdx.x * 64;          // row base in Wcat (768 rows)
    const int wm = (warp >> 1) * 32, wn = (warp & 1) * 32;
    const int which = blockIdx.x >> 2;
    __half* dst = which == 0 ? Qd : which == 1 ? Kd : Vd;
    const int nloc = (blockIdx.x & 3) * 64;
    const float oscale = (which == 0) ? 0.17677669529663687f * 1.4426950408889634f : 1.0f;

    float acc[2][4][4];
#pragma unroll
    for (int mt = 0; mt < 2; ++mt)
#pragma unroll
        for (int nt = 0; nt < 4; ++nt)
#pragma unroll
            for (int i = 0; i < 4; ++i) acc[mt][nt][i] = 0.f;

    GEMM_BODY(X, Wcat, n0w, acc)

#pragma unroll
    for (int mt = 0; mt < 2; ++mt) {
#pragma unroll
        for (int nt = 0; nt < 4; ++nt) {
            int r = m0 + wm + mt * 16 + g;
            int c = nloc + wn + nt * 8 + 2 * l;
            *(__half2*)(dst + (size_t)r * 256 + c) =
                __floats2half2_rn(acc[mt][nt][0] * oscale, acc[mt][nt][1] * oscale);
            *(__half2*)(dst + (size_t)(r + 8) * 256 + c) =
                __floats2half2_rn(acc[mt][nt][2] * oscale, acc[mt][nt][3] * oscale);
        }
    }
}

// Output GEMM: fp32 out, 128x64 tiles, grid (4, 128)
__global__ __launch_bounds__(256, 3) void gemm_out(const __half* __restrict__ X,
                                                   const __half* __restrict__ W,
                                                   float* __restrict__ C)
{
    __shared__ __half Xs[2][128 * 40];
    __shared__ __half Ws[2][64 * 40];

    const int t = threadIdx.x, warp = t >> 5, lane = t & 31;
    const int g = lane >> 2, l = lane & 3;
    const int m0 = blockIdx.y * 128;
    const int n0w = blockIdx.x * 64;
    const int wm = (warp >> 1) * 32, wn = (warp & 1) * 32;

    float acc[2][4][4];
#pragma unroll
    for (int mt = 0; mt < 2; ++mt)
#pragma unroll
        for (int nt = 0; nt < 4; ++nt)
#pragma unroll
            for (int i = 0; i < 4; ++i) acc[mt][nt][i] = 0.f;

    GEMM_BODY(X, W, n0w, acc)

#pragma unroll
    for (int mt = 0; mt < 2; ++mt) {
#pragma unroll
        for (int nt = 0; nt < 4; ++nt) {
            int r = m0 + wm + mt * 16 + g;
            int c = n0w + wn + nt * 8 + 2 * l;
            *(float2*)(C + (size_t)r * 256 + c)       = make_float2(acc[mt][nt][0], acc[mt][nt][1]);
            *(float2*)(C + (size_t)(r + 8) * 256 + c) = make_float2(acc[mt][nt][2], acc[mt][nt][3]);
        }
    }
}

// ----------------------------------------------------------------------------
// Attention (fp16) — v8 logic, occupancy 4 -> 5 blocks/SM.
// ----------------------------------------------------------------------------
#define KLDH 40   // K/V row stride halves (80B) -> conflict-free
#define ELDH 72   // em row stride halves (144B) -> conflict-free

__global__ __launch_bounds__(128, 5) void attn_f16(
    const __half* __restrict__ Qh, const __half* __restrict__ Kh,
    const __half* __restrict__ Vh, const __half* __restrict__ em,
    const float* __restrict__ We, __half* __restrict__ AOh)
{
    __shared__ __half Ks[2][64 * KLDH];
    __shared__ __half Vs[2][64 * KLDH];
    __shared__ __half Es[2][64 * ELDH];

    const int t = threadIdx.x, warp = t >> 5, lane = t & 31;
    const int g = lane >> 2, l = lane & 3;
    const int bh = blockIdx.y;
    const int b  = bh >> 3, hh = bh & 7;
    const int q0 = blockIdx.x * 64;
    const size_t bN = (size_t)b * NSEQ;
    const int R0 = warp * 16 + g;
    const float we = We[hh] * 1.4426950408889634f;   // log2 domain

    const int arow = warp * 16 + (lane & 7) + ((lane >> 3) & 1) * 8;
    const int acol = ((lane >> 4) << 3);
    const int krow = (lane & 7);
    const int kcol = ((lane >> 3) << 3);

#pragma unroll
    for (int i = 0; i < 2; ++i) {
        int idx = t + i * 128;
        int row = idx >> 2, c = idx & 3;
        uint4 v = *(const uint4*)(Qh + ((bN + q0 + row) * DMODEL) + hh * HDIM + c * 8);
        *(uint4*)&Ks[0][row * KLDH + c * 8] = v;
    }
    __syncthreads();

    unsigned qa[2][4];
    ldsm4(qa[0][0], qa[0][1], qa[0][2], qa[0][3], Ks[0] + arow * KLDH + acol);
    ldsm4(qa[1][0], qa[1][1], qa[1][2], qa[1][3], Ks[0] + arow * KLDH + 16 + acol);
    __syncthreads();

    float m0r = -1e30f, m1r = -1e30f, l0r = 0.f, l1r = 0.f;
    float o[4][4];
#pragma unroll
    for (int nt = 0; nt < 4; ++nt)
#pragma unroll
        for (int i = 0; i < 4; ++i) o[nt][i] = 0.f;

    const int kv_row = t >> 2, kv_c = t & 3;
    const int em_row = t >> 3, em_c = t & 7;

#pragma unroll
    for (int i = 0; i < 2; ++i) {
        int row = kv_row + i * 32;
        cp16(&Ks[0][row * KLDH + kv_c * 8], Kh + (bN + row) * DMODEL + hh * HDIM + kv_c * 8);
        cp16(&Vs[0][row * KLDH + kv_c * 8], Vh + (bN + row) * DMODEL + hh * HDIM + kv_c * 8);
    }
#pragma unroll
    for (int i = 0; i < 4; ++i) {
        int row = em_row + i * 16;
        cp16(&Es[0][row * ELDH + em_c * 8], em + ((bN + q0 + row) * NSEQ) + em_c * 8);
    }
    CP_COMMIT();

    for (int it = 0; it < 8; ++it) {
        CP_WAIT0();
        __syncthreads();
        if (it < 7) {
            int jt = (it + 1) * 64, buf = (it + 1) & 1;
#pragma unroll
            for (int i = 0; i < 2; ++i) {
                int row = kv_row + i * 32;
                cp16(&Ks[buf][row * KLDH + kv_c * 8],
                     Kh + (bN + jt + row) * DMODEL + hh * HDIM + kv_c * 8);
                cp16(&Vs[buf][row * KLDH + kv_c * 8],
                     Vh + (bN + jt + row) * DMODEL + hh * HDIM + kv_c * 8);
            }
#pragma unroll
            for (int i = 0; i < 4; ++i) {
                int row = em_row + i * 16;
                cp16(&Es[buf][row * ELDH + em_c * 8],
                     em + ((bN + q0 + row) * NSEQ) + jt + em_c * 8);
            }
        }
        CP_COMMIT();

        const __half* Kb = Ks[it & 1];
        const __half* Eb = Es[it & 1];
        const __half* Vb = Vs[it & 1];

        float s[8][4];
#pragma unroll
        for (int nt = 0; nt < 8; ++nt) {
            s[nt][0] = s[nt][1] = s[nt][2] = s[nt][3] = 0.f;
            unsigned b0, b1, b2, b3;
            ldsm4(b0, b1, b2, b3, Kb + (8 * nt + krow) * KLDH + kcol);
            mma_f16(s[nt], qa[0][0], qa[0][1], qa[0][2], qa[0][3], b0, b1);
            mma_f16(s[nt], qa[1][0], qa[1][1], qa[1][2], qa[1][3], b2, b3);
        }

        float mn0 = m0r, mn1 = m1r;
#pragma unroll
        for (int i = 0; i < 4; ++i) {
            unsigned e0, e1, e2, e3;
            ldsm4(e0, e1, e2, e3, Eb + arow * ELDH + i * 16 + acol);
            float2 f0 = __half22float2(*(__half2*)&e0);
            float2 f1 = __half22float2(*(__half2*)&e1);
            float2 f2 = __half22float2(*(__half2*)&e2);
            float2 f3 = __half22float2(*(__half2*)&e3);
            int n0i = 2 * i, n1i = 2 * i + 1;
            s[n0i][0] = fmaxf(fmaf(we, f0.x, s[n0i][0]), -1e30f);
            s[n0i][1] = fmaxf(fmaf(we, f0.y, s[n0i][1]), -1e30f);
            s[n0i][2] = fmaxf(fmaf(we, f1.x, s[n0i][2]), -1e30f);
            s[n0i][3] = fmaxf(fmaf(we, f1.y, s[n0i][3]), -1e30f);
            s[n1i][0] = fmaxf(fmaf(we, f2.x, s[n1i][0]), -1e30f);
            s[n1i][1] = fmaxf(fmaf(we, f2.y, s[n1i][1]), -1e30f);
            s[n1i][2] = fmaxf(fmaf(we, f3.x, s[n1i][2]), -1e30f);
            s[n1i][3] = fmaxf(fmaf(we, f3.y, s[n1i][3]), -1e30f);
            mn0 = fmaxf(mn0, fmaxf(fmaxf(s[n0i][0], s[n0i][1]), fmaxf(s[n1i][0], s[n1i][1])));
            mn1 = fmaxf(mn1, fmaxf(fmaxf(s[n0i][2], s[n0i][3]), fmaxf(s[n1i][2], s[n1i][3])));
        }
        mn0 = fmaxf(mn0, __shfl_xor_sync(0xffffffff, mn0, 1));
        mn0 = fmaxf(mn0, __shfl_xor_sync(0xffffffff, mn0, 2));
        mn1 = fmaxf(mn1, __shfl_xor_sync(0xffffffff, mn1, 1));
        mn1 = fmaxf(mn1, __shfl_xor_sync(0xffffffff, mn1, 2));

        float corr0 = exp2f(m0r - mn0);
        float corr1 = exp2f(m1r - mn1);
        m0r = mn0; m1r = mn1;

        unsigned ph[8][2];
        float ps0 = 0.f, ps1 = 0.f;
#pragma unroll
        for (int nt = 0; nt < 8; ++nt) {
            __half2 x01 = __floats2half2_rn(s[nt][0] - mn0, s[nt][1] - mn0);
            __half2 x23 = __floats2half2_rn(s[nt][2] - mn1, s[nt][3] - mn1);
            __half2 p01 = h2exp2(x01);
            __half2 p23 = h2exp2(x23);
            ph[nt][0] = *(unsigned*)&p01;
            ph[nt][1] = *(unsigned*)&p23;
            float2 f01 = __half22float2(p01);
            float2 f23 = __half22float2(p23);
            ps0 += f01.x + f01.y;
            ps1 += f23.x + f23.y;
        }
        ps0 += __shfl_xor_sync(0xffffffff, ps0, 1);
        ps0 += __shfl_xor_sync(0xffffffff, ps0, 2);
        ps1 += __shfl_xor_sync(0xffffffff, ps1, 1);
        ps1 += __shfl_xor_sync(0xffffffff, ps1, 2);
        l0r = l0r * corr0 + ps0;
        l1r = l1r * corr1 + ps1;

#pragma unroll
        for (int nt = 0; nt < 4; ++nt) {
            o[nt][0] *= corr0; o[nt][1] *= corr0;
            o[nt][2] *= corr1; o[nt][3] *= corr1;
        }

        const int vkey = ((lane >> 3) & 1) << 3;
        const int vd   = ((lane >> 4) & 1) << 3;
        const int vr   = lane & 7;
#pragma unroll
        for (int kc = 0; kc < 4; ++kc) {
            unsigned a0 = ph[2 * kc][0];
            unsigned a1 = ph[2 * kc][1];
            unsigned a2 = ph[2 * kc + 1][0];
            unsigned a3 = ph[2 * kc + 1][1];
            unsigned v0, v1, v2, v3, v4, v5, v6, v7;
            const __half* basep = Vb + (16 * kc + vkey + vr) * KLDH + vd;
            ldsm4t(v0, v1, v2, v3, basep);
            ldsm4t(v4, v5, v6, v7, basep + 16);
            mma_f16(o[0], a0, a1, a2, a3, v0, v1);
            mma_f16(o[1], a0, a1, a2, a3, v2, v3);
            mma_f16(o[2], a0, a1, a2, a3, v4, v5);
            mma_f16(o[3], a0, a1, a2, a3, v6, v7);
        }
    }

    const float inv0 = 1.0f / l0r;
    const float inv1 = 1.0f / l1r;
#pragma unroll
    for (int nt = 0; nt < 4; ++nt) {
        int c = hh * HDIM + nt * 8 + 2 * l;
        *(__half2*)(AOh + (bN + q0 + R0) * DMODEL + c) =
            __floats2half2_rn(o[nt][0] * inv0, o[nt][1] * inv0);
        *(__half2*)(AOh + (bN + q0 + R0 + 8) * DMODEL + c) =
            __floats2half2_rn(o[nt][2] * inv1, o[nt][3] * inv1);
    }
}

// ----------------------------------------------------------------------------
// launch
// ----------------------------------------------------------------------------
extern "C" void kernel_launch(void* const* d_in, const int* in_sizes, int n_in,
                              void* d_out, int out_size)
{
    const float* h    = (const float*)d_in[0];
    const float* edge = (const float*)d_in[1];
    const int*   mask = (const int*)  d_in[2];
    const float* Wq   = (const float*)d_in[3];
    const float* Wk   = (const float*)d_in[4];
    const float* Wv   = (const float*)d_in[5];
    const float* We   = (const float*)d_in[6];
    const float* Wo   = (const float*)d_in[7];
    float* out = (float*)d_out;

    __half *h16, *q16, *k16, *v16, *ao16, *emh, *w16;
    cudaGetSymbolAddress((void**)&h16,  g_h16);
    cudaGetSymbolAddress((void**)&q16,  g_q16);
    cudaGetSymbolAddress((void**)&k16,  g_k16);
    cudaGetSymbolAddress((void**)&v16,  g_v16);
    cudaGetSymbolAddress((void**)&ao16, g_ao16);
    cudaGetSymbolAddress((void**)&emh,  g_em);
    cudaGetSymbolAddress((void**)&w16,  g_w16);

    prep_hw<<<(N_HW8 + 255) / 256, 256>>>(h, Wq, Wk, Wv, Wo, h16, w16);

    // gemm rows in by<128; em-prep streaming blocks in by in [128,160)
    gemm_qkv<<<dim3(12, 160), 256>>>(h16, w16, q16, k16, v16, edge, mask, emh);

    attn_f16<<<dim3(NSEQ / 64, BATCH * NHEAD), 128>>>(q16, k16, v16, emh, We, ao16);

    gemm_out<<<dim3(4, MROWS / 128), 256>>>(ao16, w16 + 3 * DMODEL * DMODEL, out);
}

// round 11
// speedup vs baseline: 2.3750x; 1.0714x over previous
#include <cuda_runtime.h>
#include <cuda_fp16.h>
#include <math.h>

// ----------------------------------------------------------------------------
// EdgeBiasedAttention — v11: v8 GEMM config (128x128, 4-stage) restored +
// em-prep fused into gemm_qkv as leading streaming blocks; attn occ 5.
// B=32, N=512, D=256, H=8, HD=32
// ----------------------------------------------------------------------------

#define BATCH 32
#define NSEQ  512
#define DMODEL 256
#define NHEAD 8
#define HDIM  32
#define MROWS (BATCH * NSEQ)  // 16384

#define N_H8 (MROWS * DMODEL / 8)          // 524288
#define N_W8 (DMODEL * DMODEL / 8)         // 8192
#define N_E8 (BATCH * NSEQ * NSEQ / 8)     // 1048576
#define N_HW8 (N_H8 + 4 * N_W8)            // 557056

// fp16 scratch
__device__ __half g_h16 [MROWS * DMODEL];
__device__ __half g_q16 [MROWS * DMODEL];
__device__ __half g_k16 [MROWS * DMODEL];
__device__ __half g_v16 [MROWS * DMODEL];
__device__ __half g_ao16[MROWS * DMODEL];
__device__ __half g_em  [BATCH * NSEQ * NSEQ];   // masked edge (NaN = masked)
__device__ __half g_w16 [4 * DMODEL * DMODEL];   // Wq, Wk, Wv, Wo fp16

// ---------------- helpers ----------------
__device__ __forceinline__ void mma_f16(float c[4],
                                        unsigned a0, unsigned a1, unsigned a2, unsigned a3,
                                        unsigned b0, unsigned b1)
{
    asm volatile(
        "mma.sync.aligned.m16n8k16.row.col.f32.f16.f16.f32 "
        "{%0,%1,%2,%3}, {%4,%5,%6,%7}, {%8,%9}, {%0,%1,%2,%3};"
        : "+f"(c[0]), "+f"(c[1]), "+f"(c[2]), "+f"(c[3])
        : "r"(a0), "r"(a1), "r"(a2), "r"(a3), "r"(b0), "r"(b1));
}

__device__ __forceinline__ void cp16(void* sdst, const void* gsrc) {
    unsigned s = (unsigned)__cvta_generic_to_shared(sdst);
    asm volatile("cp.async.cg.shared.global [%0], [%1], 16;" :: "r"(s), "l"(gsrc));
}
#define CP_COMMIT() asm volatile("cp.async.commit_group;")
#define CP_WAIT0()  asm volatile("cp.async.wait_group 0;" ::: "memory")
#define CP_WAIT2()  asm volatile("cp.async.wait_group 2;" ::: "memory")

__device__ __forceinline__ void ldsm4(unsigned& r0, unsigned& r1, unsigned& r2, unsigned& r3,
                                      const __half* p)
{
    unsigned s = (unsigned)__cvta_generic_to_shared(p);
    asm volatile("ldmatrix.sync.aligned.m8n8.x4.shared.b16 {%0,%1,%2,%3}, [%4];"
                 : "=r"(r0), "=r"(r1), "=r"(r2), "=r"(r3) : "r"(s));
}
__device__ __forceinline__ void ldsm4t(unsigned& r0, unsigned& r1, unsigned& r2, unsigned& r3,
                                       const __half* p)
{
    unsigned s = (unsigned)__cvta_generic_to_shared(p);
    asm volatile("ldmatrix.sync.aligned.m8n8.x4.trans.shared.b16 {%0,%1,%2,%3}, [%4];"
                 : "=r"(r0), "=r"(r1), "=r"(r2), "=r"(r3) : "r"(s));
}

__device__ __forceinline__ uint4 pack8(float4 a, float4 b) {
    uint4 o;
    __half2 h0 = __floats2half2_rn(a.x, a.y);
    __half2 h1 = __floats2half2_rn(a.z, a.w);
    __half2 h2 = __floats2half2_rn(b.x, b.y);
    __half2 h3 = __floats2half2_rn(b.z, b.w);
    o.x = *(unsigned*)&h0; o.y = *(unsigned*)&h1;
    o.z = *(unsigned*)&h2; o.w = *(unsigned*)&h3;
    return o;
}

// ---------------- preprocessing: h + weights only (em fused into gemm_qkv) --
__global__ __launch_bounds__(256) void prep_hw(
    const float* __restrict__ h,
    const float* __restrict__ Wq, const float* __restrict__ Wk,
    const float* __restrict__ Wv, const float* __restrict__ Wo,
    __half* __restrict__ h16, __half* __restrict__ w16)
{
    int i = blockIdx.x * 256 + threadIdx.x;
    if (i < N_H8) {
        const float4* s = (const float4*)h + (size_t)i * 2;
        ((uint4*)h16)[i] = pack8(s[0], s[1]);
    } else if (i < N_HW8) {
        int j = i - N_H8;
        int which = j >> 13, off = j & (N_W8 - 1);
        const float* W = which == 0 ? Wq : which == 1 ? Wk : which == 2 ? Wv : Wo;
        const float4* s = (const float4*)W + (size_t)off * 2;
        ((uint4*)w16)[(size_t)which * N_W8 + off] = pack8(s[0], s[1]);
    }
}

// ----------------------------------------------------------------------------
// GEMM core: 128x128 tile, BK=32, 4-stage cp.async pipeline, ldmatrix frags.
// Dynamic smem: Xs[4][128*40], Ws[4][128*40]  (81920 B)
// ----------------------------------------------------------------------------
#define GSTG (128 * 40)
#define GEMM_SMEM_BYTES (8 * GSTG * 2)

#define GEMM_BODY(X, W, ACC)                                                         \
    __half* Xs = gsm;                                                                \
    __half* Ws = gsm + 4 * GSTG;                                                     \
    const int srow = t >> 2, sc = t & 3;                                             \
    _Pragma("unroll")                                                                \
    for (int st = 0; st < 3; ++st) {                                                 \
        int k0 = st * 32;                                                            \
        _Pragma("unroll")                                                            \
        for (int i = 0; i < 2; ++i) {                                                \
            int row = srow + i * 64;                                                 \
            cp16(Xs + st * GSTG + row * 40 + sc * 8, X + (size_t)(m0 + row) * 256 + k0 + sc * 8); \
            cp16(Ws + st * GSTG + row * 40 + sc * 8, W + (size_t)(n0 + row) * 256 + k0 + sc * 8); \
        }                                                                            \
        CP_COMMIT();                                                                 \
    }                                                                                \
    const int arow = wm + (lane & 7) + ((lane >> 3) & 1) * 8;                        \
    const int acol = ((lane >> 4) << 3);                                             \
    const int brow = wn + ((lane >> 4) << 3) + (lane & 7);                           \
    const int bcol = ((lane >> 3) & 1) << 3;                                         \
    for (int p = 0; p < 8; ++p) {                                                    \
        CP_WAIT2();                                                                  \
        __syncthreads();                                                             \
        if (p < 5) {                                                                 \
            int k0 = (p + 3) * 32, buf = (p + 3) & 3;                                \
            _Pragma("unroll")                                                        \
            for (int i = 0; i < 2; ++i) {                                            \
                int row = srow + i * 64;                                             \
                cp16(Xs + buf * GSTG + row * 40 + sc * 8, X + (size_t)(m0 + row) * 256 + k0 + sc * 8); \
                cp16(Ws + buf * GSTG + row * 40 + sc * 8, W + (size_t)(n0 + row) * 256 + k0 + sc * 8); \
            }                                                                        \
        }                                                                            \
        CP_COMMIT();                                                                 \
        const __half* Xb = Xs + (p & 3) * GSTG;                                      \
        const __half* Wb = Ws + (p & 3) * GSTG;                                      \
        _Pragma("unroll")                                                            \
        for (int kc = 0; kc < 2; ++kc) {                                             \
            unsigned a[4][4], bb[4][2];                                              \
            _Pragma("unroll")                                                        \
            for (int mt = 0; mt < 4; ++mt)                                           \
                ldsm4(a[mt][0], a[mt][1], a[mt][2], a[mt][3],                        \
                      Xb + (arow + mt * 16) * 40 + kc * 16 + acol);                  \
            _Pragma("unroll")                                                        \
            for (int np = 0; np < 2; ++np)                                           \
                ldsm4(bb[np * 2][0], bb[np * 2][1], bb[np * 2 + 1][0], bb[np * 2 + 1][1], \
                      Wb + (brow + np * 16) * 40 + kc * 16 + bcol);                  \
            _Pragma("unroll")                                                        \
            for (int mt = 0; mt < 4; ++mt)                                           \
                _Pragma("unroll")                                                    \
                for (int nt = 0; nt < 4; ++nt)                                       \
                    mma_f16(ACC[mt][nt], a[mt][0], a[mt][1], a[mt][2], a[mt][3],     \
                            bb[nt][0], bb[nt][1]);                                   \
        }                                                                            \
    }

// Fused QKV GEMM + em preprocessing.
// grid (6, 160): by<32 -> em-prep streaming blocks (scheduled FIRST, overlap
// with the gemm wave); by>=32 -> gemm rows m0=(by-32)*128. bx>>1 selects
// Q/K/V; (bx&1)*128 is n-offset. Q output pre-scaled.
__global__ __launch_bounds__(256, 2) void gemm_qkv(
    const __half* __restrict__ X, const __half* __restrict__ Wcat,
    __half* __restrict__ Qd, __half* __restrict__ Kd, __half* __restrict__ Vd,
    const float* __restrict__ edge, const int* __restrict__ mask,
    __half* __restrict__ em)
{
    extern __shared__ __half gsm[];
    const int t = threadIdx.x;

    if (blockIdx.y < 32) {
        // ---- em preprocessing block (pure streaming) ----
        const float QNAN = __int_as_float(0x7fc00000);
        int chunk = blockIdx.y * 6 + blockIdx.x;             // 0..191
        for (int j = chunk * 256 + t; j < N_E8; j += 192 * 256) {
            const float4* es = (const float4*)edge + (size_t)j * 2;
            const int4*   ms = (const int4*)mask + (size_t)j * 2;
            float4 e0 = es[0], e1 = es[1];
            int4   m0v = ms[0], m1v = ms[1];
            float4 f0 = make_float4(m0v.x ? e0.x : QNAN, m0v.y ? e0.y : QNAN,
                                    m0v.z ? e0.z : QNAN, m0v.w ? e0.w : QNAN);
            float4 f1 = make_float4(m1v.x ? e1.x : QNAN, m1v.y ? e1.y : QNAN,
                                    m1v.z ? e1.z : QNAN, m1v.w ? e1.w : QNAN);
            ((uint4*)em)[j] = pack8(f0, f1);
        }
        return;
    }

    const int warp = t >> 5, lane = t & 31;
    const int g = lane >> 2, l = lane & 3;
    const int m0 = (blockIdx.y - 32) * 128, n0 = blockIdx.x * 128;
    const int wm = (warp >> 2) * 64, wn = (warp & 3) * 32;
    const int which = blockIdx.x >> 1;
    __half* dst = which == 0 ? Qd : which == 1 ? Kd : Vd;
    const int nloc = n0 & 255;
    const float oscale = (which == 0) ? 0.17677669529663687f * 1.4426950408889634f : 1.0f;

    float acc[4][4][4];
#pragma unroll
    for (int mt = 0; mt < 4; ++mt)
#pragma unroll
        for (int nt = 0; nt < 4; ++nt)
#pragma unroll
            for (int i = 0; i < 4; ++i) acc[mt][nt][i] = 0.f;

    GEMM_BODY(X, Wcat, acc)

#pragma unroll
    for (int mt = 0; mt < 4; ++mt) {
#pragma unroll
        for (int nt = 0; nt < 4; ++nt) {
            int r = m0 + wm + mt * 16 + g;
            int c = nloc + wn + nt * 8 + 2 * l;
            *(__half2*)(dst + (size_t)r * 256 + c) =
                __floats2half2_rn(acc[mt][nt][0] * oscale, acc[mt][nt][1] * oscale);
            *(__half2*)(dst + (size_t)(r + 8) * 256 + c) =
                __floats2half2_rn(acc[mt][nt][2] * oscale, acc[mt][nt][3] * oscale);
        }
    }
}

// Output GEMM: fp32 out, 128x128 tiles, grid (2, 128)
__global__ __launch_bounds__(256, 2) void gemm_out(const __half* __restrict__ X,
                                                   const __half* __restrict__ W,
                                                   float* __restrict__ C)
{
    extern __shared__ __half gsm[];

    const int t = threadIdx.x, warp = t >> 5, lane = t & 31;
    const int g = lane >> 2, l = lane & 3;
    const int m0 = blockIdx.y * 128, n0 = blockIdx.x * 128;
    const int wm = (warp >> 2) * 64, wn = (warp & 3) * 32;

    float acc[4][4][4];
#pragma unroll
    for (int mt = 0; mt < 4; ++mt)
#pragma unroll
        for (int nt = 0; nt < 4; ++nt)
#pragma unroll
            for (int i = 0; i < 4; ++i) acc[mt][nt][i] = 0.f;

    GEMM_BODY(X, W, acc)

#pragma unroll
    for (int mt = 0; mt < 4; ++mt) {
#pragma unroll
        for (int nt = 0; nt < 4; ++nt) {
            int r = m0 + wm + mt * 16 + g;
            int c = n0 + wn + nt * 8 + 2 * l;
            *(float2*)(C + (size_t)r * 256 + c)       = make_float2(acc[mt][nt][0], acc[mt][nt][1]);
            *(float2*)(C + (size_t)(r + 8) * 256 + c) = make_float2(acc[mt][nt][2], acc[mt][nt][3]);
        }
    }
}

// ----------------------------------------------------------------------------
// Attention (fp16) — v8 logic, occupancy 5 blocks/SM.
// ----------------------------------------------------------------------------
#define KLDH 40   // K/V row stride halves (80B) -> conflict-free
#define ELDH 72   // em row stride halves (144B) -> conflict-free

__global__ __launch_bounds__(128, 5) void attn_f16(
    const __half* __restrict__ Qh, const __half* __restrict__ Kh,
    const __half* __restrict__ Vh, const __half* __restrict__ em,
    const float* __restrict__ We, __half* __restrict__ AOh)
{
    __shared__ __half Ks[2][64 * KLDH];
    __shared__ __half Vs[2][64 * KLDH];
    __shared__ __half Es[2][64 * ELDH];

    const int t = threadIdx.x, warp = t >> 5, lane = t & 31;
    const int g = lane >> 2, l = lane & 3;
    const int bh = blockIdx.y;
    const int b  = bh >> 3, hh = bh & 7;
    const int q0 = blockIdx.x * 64;
    const size_t bN = (size_t)b * NSEQ;
    const int R0 = warp * 16 + g;
    const float we = We[hh] * 1.4426950408889634f;   // log2 domain

    const int arow = warp * 16 + (lane & 7) + ((lane >> 3) & 1) * 8;
    const int acol = ((lane >> 4) << 3);
    const int krow = (lane & 7);
    const int kcol = ((lane >> 3) << 3);

#pragma unroll
    for (int i = 0; i < 2; ++i) {
        int idx = t + i * 128;
        int row = idx >> 2, c = idx & 3;
        uint4 v = *(const uint4*)(Qh + ((bN + q0 + row) * DMODEL) + hh * HDIM + c * 8);
        *(uint4*)&Ks[0][row * KLDH + c * 8] = v;
    }
    __syncthreads();

    unsigned qa[2][4];
    ldsm4(qa[0][0], qa[0][1], qa[0][2], qa[0][3], Ks[0] + arow * KLDH + acol);
    ldsm4(qa[1][0], qa[1][1], qa[1][2], qa[1][3], Ks[0] + arow * KLDH + 16 + acol);
    __syncthreads();

    float m0r = -1e30f, m1r = -1e30f, l0r = 0.f, l1r = 0.f;
    float o[4][4];
#pragma unroll
    for (int nt = 0; nt < 4; ++nt)
#pragma unroll
        for (int i = 0; i < 4; ++i) o[nt][i] = 0.f;

    const int kv_row = t >> 2, kv_c = t & 3;
    const int em_row = t >> 3, em_c = t & 7;

#pragma unroll
    for (int i = 0; i < 2; ++i) {
        int row = kv_row + i * 32;
        cp16(&Ks[0][row * KLDH + kv_c * 8], Kh + (bN + row) * DMODEL + hh * HDIM + kv_c * 8);
        cp16(&Vs[0][row * KLDH + kv_c * 8], Vh + (bN + row) * DMODEL + hh * HDIM + kv_c * 8);
    }
#pragma unroll
    for (int i = 0; i < 4; ++i) {
        int row = em_row + i * 16;
        cp16(&Es[0][row * ELDH + em_c * 8], em + ((bN + q0 + row) * NSEQ) + em_c * 8);
    }
    CP_COMMIT();

    for (int it = 0; it < 8; ++it) {
        CP_WAIT0();
        __syncthreads();
        if (it < 7) {
            int jt = (it + 1) * 64, buf = (it + 1) & 1;
#pragma unroll
            for (int i = 0; i < 2; ++i) {
                int row = kv_row + i * 32;
                cp16(&Ks[buf][row * KLDH + kv_c * 8],
                     Kh + (bN + jt + row) * DMODEL + hh * HDIM + kv_c * 8);
                cp16(&Vs[buf][row * KLDH + kv_c * 8],
                     Vh + (bN + jt + row) * DMODEL + hh * HDIM + kv_c * 8);
            }
#pragma unroll
            for (int i = 0; i < 4; ++i) {
                int row = em_row + i * 16;
                cp16(&Es[buf][row * ELDH + em_c * 8],
                     em + ((bN + q0 + row) * NSEQ) + jt + em_c * 8);
            }
        }
        CP_COMMIT();

        const __half* Kb = Ks[it & 1];
        const __half* Eb = Es[it & 1];
        const __half* Vb = Vs[it & 1];

        float s[8][4];
#pragma unroll
        for (int nt = 0; nt < 8; ++nt) {
            s[nt][0] = s[nt][1] = s[nt][2] = s[nt][3] = 0.f;
            unsigned b0, b1, b2, b3;
            ldsm4(b0, b1, b2, b3, Kb + (8 * nt + krow) * KLDH + kcol);
            mma_f16(s[nt], qa[0][0], qa[0][1], qa[0][2], qa[0][3], b0, b1);
            mma_f16(s[nt], qa[1][0], qa[1][1], qa[1][2], qa[1][3], b2, b3);
        }

        float mn0 = m0r, mn1 = m1r;
#pragma unroll
        for (int i = 0; i < 4; ++i) {
            unsigned e0, e1, e2, e3;
            ldsm4(e0, e1, e2, e3, Eb + arow * ELDH + i * 16 + acol);
            float2 f0 = __half22float2(*(__half2*)&e0);
            float2 f1 = __half22float2(*(__half2*)&e1);
            float2 f2 = __half22float2(*(__half2*)&e2);
            float2 f3 = __half22float2(*(__half2*)&e3);
            int n0i = 2 * i, n1i = 2 * i + 1;
            s[n0i][0] = fmaxf(fmaf(we, f0.x, s[n0i][0]), -1e30f);
            s[n0i][1] = fmaxf(fmaf(we, f0.y, s[n0i][1]), -1e30f);
            s[n0i][2] = fmaxf(fmaf(we, f1.x, s[n0i][2]), -1e30f);
            s[n0i][3] = fmaxf(fmaf(we, f1.y, s[n0i][3]), -1e30f);
            s[n1i][0] = fmaxf(fmaf(we, f2.x, s[n1i][0]), -1e30f);
            s[n1i][1] = fmaxf(fmaf(we, f2.y, s[n1i][1]), -1e30f);
            s[n1i][2] = fmaxf(fmaf(we, f3.x, s[n1i][2]), -1e30f);
            s[n1i][3] = fmaxf(fmaf(we, f3.y, s[n1i][3]), -1e30f);
            mn0 = fmaxf(mn0, fmaxf(fmaxf(s[n0i][0], s[n0i][1]), fmaxf(s[n1i][0], s[n1i][1])));
            mn1 = fmaxf(mn1, fmaxf(fmaxf(s[n0i][2], s[n0i][3]), fmaxf(s[n1i][2], s[n1i][3])));
        }
        mn0 = fmaxf(mn0, __shfl_xor_sync(0xffffffff, mn0, 1));
        mn0 = fmaxf(mn0, __shfl_xor_sync(0xffffffff, mn0, 2));
        mn1 = fmaxf(mn1, __shfl_xor_sync(0xffffffff, mn1, 1));
        mn1 = fmaxf(mn1, __shfl_xor_sync(0xffffffff, mn1, 2));

        float corr0 = exp2f(m0r - mn0);
        float corr1 = exp2f(m1r - mn1);
        m0r = mn0; m1r = mn1;

        unsigned ph[8][2];
        float ps0 = 0.f, ps1 = 0.f;
#pragma unroll
        for (int nt = 0; nt < 8; ++nt) {
            __half2 x01 = __floats2half2_rn(s[nt][0] - mn0, s[nt][1] - mn0);
            __half2 x23 = __floats2half2_rn(s[nt][2] - mn1, s[nt][3] - mn1);
            __half2 p01 = h2exp2(x01);
            __half2 p23 = h2exp2(x23);
            ph[nt][0] = *(unsigned*)&p01;
            ph[nt][1] = *(unsigned*)&p23;
            float2 f01 = __half22float2(p01);
            float2 f23 = __half22float2(p23);
            ps0 += f01.x + f01.y;
            ps1 += f23.x + f23.y;
        }
        ps0 += __shfl_xor_sync(0xffffffff, ps0, 1);
        ps0 += __shfl_xor_sync(0xffffffff, ps0, 2);
        ps1 += __shfl_xor_sync(0xffffffff, ps1, 1);
        ps1 += __shfl_xor_sync(0xffffffff, ps1, 2);
        l0r = l0r * corr0 + ps0;
        l1r = l1r * corr1 + ps1;

#pragma unroll
        for (int nt = 0; nt < 4; ++nt) {
            o[nt][0] *= corr0; o[nt][1] *= corr0;
            o[nt][2] *= corr1; o[nt][3] *= corr1;
        }

        const int vkey = ((lane >> 3) & 1) << 3;
        const int vd   = ((lane >> 4) & 1) << 3;
        const int vr   = lane & 7;
#pragma unroll
        for (int kc = 0; kc < 4; ++kc) {
            unsigned a0 = ph[2 * kc][0];
            unsigned a1 = ph[2 * kc][1];
            unsigned a2 = ph[2 * kc + 1][0];
            unsigned a3 = ph[2 * kc + 1][1];
            unsigned v0, v1, v2, v3, v4, v5, v6, v7;
            const __half* basep = Vb + (16 * kc + vkey + vr) * KLDH + vd;
            ldsm4t(v0, v1, v2, v3, basep);
            ldsm4t(v4, v5, v6, v7, basep + 16);
            mma_f16(o[0], a0, a1, a2, a3, v0, v1);
            mma_f16(o[1], a0, a1, a2, a3, v2, v3);
            mma_f16(o[2], a0, a1, a2, a3, v4, v5);
            mma_f16(o[3], a0, a1, a2, a3, v6, v7);
        }
    }

    const float inv0 = 1.0f / l0r;
    const float inv1 = 1.0f / l1r;
#pragma unroll
    for (int nt = 0; nt < 4; ++nt) {
        int c = hh * HDIM + nt * 8 + 2 * l;
        *(__half2*)(AOh + (bN + q0 + R0) * DMODEL + c) =
            __floats2half2_rn(o[nt][0] * inv0, o[nt][1] * inv0);
        *(__half2*)(AOh + (bN + q0 + R0 + 8) * DMODEL + c) =
            __floats2half2_rn(o[nt][2] * inv1, o[nt][3] * inv1);
    }
}

// ----------------------------------------------------------------------------
// launch
// ----------------------------------------------------------------------------
extern "C" void kernel_launch(void* const* d_in, const int* in_sizes, int n_in,
                              void* d_out, int out_size)
{
    const float* h    = (const float*)d_in[0];
    const float* edge = (const float*)d_in[1];
    const int*   mask = (const int*)  d_in[2];
    const float* Wq   = (const float*)d_in[3];
    const float* Wk   = (const float*)d_in[4];
    const float* Wv   = (const float*)d_in[5];
    const float* We   = (const float*)d_in[6];
    const float* Wo   = (const float*)d_in[7];
    float* out = (float*)d_out;

    __half *h16, *q16, *k16, *v16, *ao16, *emh, *w16;
    cudaGetSymbolAddress((void**)&h16,  g_h16);
    cudaGetSymbolAddress((void**)&q16,  g_q16);
    cudaGetSymbolAddress((void**)&k16,  g_k16);
    cudaGetSymbolAddress((void**)&v16,  g_v16);
    cudaGetSymbolAddress((void**)&ao16, g_ao16);
    cudaGetSymbolAddress((void**)&emh,  g_em);
    cudaGetSymbolAddress((void**)&w16,  g_w16);

    cudaFuncSetAttribute(gemm_qkv, cudaFuncAttributeMaxDynamicSharedMemorySize, GEMM_SMEM_BYTES);
    cudaFuncSetAttribute(gemm_out, cudaFuncAttributeMaxDynamicSharedMemorySize, GEMM_SMEM_BYTES);

    prep_hw<<<(N_HW8 + 255) / 256, 256>>>(h, Wq, Wk, Wv, Wo, h16, w16);

    // by<32: em-prep streaming blocks (first); by>=32: 128x128 gemm tiles
    gemm_qkv<<<dim3(6, 160), 256, GEMM_SMEM_BYTES>>>(h16, w16, q16, k16, v16, edge, mask, emh);

    attn_f16<<<dim3(NSEQ / 64, BATCH * NHEAD), 128>>>(q16, k16, v16, emh, We, ao16);

    gemm_out<<<dim3(2, MROWS / 128), 256, GEMM_SMEM_BYTES>>>(ao16, w16 + 3 * DMODEL * DMODEL, out);
}